// round 11
// baseline (speedup 1.0000x reference)
#include <cuda_runtime.h>
#include <cuda_bf16.h>
#include <cstdint>

#define BATCH   2
#define NHEADS  12
#define SEQLEN  2048
#define DMODEL  768
#define DK      64
#define MTOT    (BATCH * SEQLEN)          // 4096

typedef __nv_bfloat16 bf16;

// ---------------- scratch (no allocations allowed) ----------------
// attention operands (bf16 hi/lo splits, produced by QKV epilogue)
__device__ __align__(256) bf16 g_qh[(size_t)BATCH * NHEADS * SEQLEN * DK];
__device__ __align__(256) bf16 g_ql[(size_t)BATCH * NHEADS * SEQLEN * DK];
__device__ __align__(256) bf16 g_kh[(size_t)BATCH * NHEADS * SEQLEN * DK];
__device__ __align__(256) bf16 g_kl[(size_t)BATCH * NHEADS * SEQLEN * DK];
__device__ __align__(256) bf16 g_vh[(size_t)BATCH * NHEADS * SEQLEN * DK];
__device__ __align__(256) bf16 g_vl[(size_t)BATCH * NHEADS * SEQLEN * DK];
__device__ __align__(256) bf16 g_ohi[(size_t)MTOT * DMODEL];
__device__ __align__(256) bf16 g_olo[(size_t)MTOT * DMODEL];
// int8 2-limb quantized operands for the projection GEMMs
__device__ __align__(256) int8_t g_qx1[(size_t)MTOT * DMODEL];
__device__ __align__(256) int8_t g_qx2[(size_t)MTOT * DMODEL];
__device__ __align__(256) int8_t g_qo1[(size_t)MTOT * DMODEL];
__device__ __align__(256) int8_t g_qo2[(size_t)MTOT * DMODEL];
__device__ __align__(256) int8_t g_qwq1[(size_t)3 * DMODEL * DMODEL];  // W_qkv^T [N][K]
__device__ __align__(256) int8_t g_qwq2[(size_t)3 * DMODEL * DMODEL];
__device__ __align__(256) int8_t g_qwo1[(size_t)DMODEL * DMODEL];      // W_out^T [N][K]
__device__ __align__(256) int8_t g_qwo2[(size_t)DMODEL * DMODEL];
__device__ float g_sx[MTOT];
__device__ float g_so[MTOT];
__device__ float g_swq[3 * DMODEL];
__device__ float g_swo[DMODEL];
__device__ float g_pm[8 * 3 * DMODEL];    // col-max partials

// ==================== helpers ====================
__device__ __forceinline__ uint32_t smem_u32(const void* p) {
    uint32_t a;
    asm("{ .reg .u64 t; cvta.to.shared.u64 t, %1; cvt.u32.u64 %0, t; }" : "=r"(a) : "l"(p));
    return a;
}
__device__ __forceinline__ void mma16816(float* d, const uint32_t* a, const uint32_t* b) {
    asm volatile(
        "mma.sync.aligned.m16n8k16.row.col.f32.bf16.bf16.f32 "
        "{%0,%1,%2,%3}, {%4,%5,%6,%7}, {%8,%9}, {%0,%1,%2,%3};"
        : "+f"(d[0]), "+f"(d[1]), "+f"(d[2]), "+f"(d[3])
        : "r"(a[0]), "r"(a[1]), "r"(a[2]), "r"(a[3]), "r"(b[0]), "r"(b[1]));
}
__device__ __forceinline__ void imma16832(int* d, const uint32_t* a, const uint32_t* b) {
    asm volatile(
        "mma.sync.aligned.m16n8k32.row.col.s32.s8.s8.s32 "
        "{%0,%1,%2,%3}, {%4,%5,%6,%7}, {%8,%9}, {%0,%1,%2,%3};"
        : "+r"(d[0]), "+r"(d[1]), "+r"(d[2]), "+r"(d[3])
        : "r"(a[0]), "r"(a[1]), "r"(a[2]), "r"(a[3]), "r"(b[0]), "r"(b[1]));
}
__device__ __forceinline__ void ldsm_x4(uint32_t* r, uint32_t addr) {
    asm volatile("ldmatrix.sync.aligned.m8n8.x4.shared.b16 {%0,%1,%2,%3}, [%4];"
                 : "=r"(r[0]), "=r"(r[1]), "=r"(r[2]), "=r"(r[3]) : "r"(addr));
}
__device__ __forceinline__ void ldsm_x4t(uint32_t* r, uint32_t addr) {
    asm volatile("ldmatrix.sync.aligned.m8n8.x4.trans.shared.b16 {%0,%1,%2,%3}, [%4];"
                 : "=r"(r[0]), "=r"(r[1]), "=r"(r[2]), "=r"(r[3]) : "r"(addr));
}
__device__ __forceinline__ void cp_async16(uint32_t dst, const void* src) {
    asm volatile("cp.async.cg.shared.global [%0], [%1], 16;" :: "r"(dst), "l"(src));
}
__device__ __forceinline__ void cp_commit() {
    asm volatile("cp.async.commit_group;" ::: "memory");
}
template <int N>
__device__ __forceinline__ void cp_wait() {
    asm volatile("cp.async.wait_group %0;" :: "n"(N) : "memory");
}
// split (x,y) fp32 -> packed bf16 hi pair + bf16 lo (residual) pair
__device__ __forceinline__ void split2(float x, float y, uint32_t& h, uint32_t& l) {
    __nv_bfloat162 hh = __floats2bfloat162_rn(x, y);
    float rx = x - __bfloat162float(hh.x);
    float ry = y - __bfloat162float(hh.y);
    __nv_bfloat162 ll = __floats2bfloat162_rn(rx, ry);
    h = *reinterpret_cast<uint32_t*>(&hh);
    l = *reinterpret_cast<uint32_t*>(&ll);
}
// quantize q (|q| <= 127) into 2 int8 limbs
__device__ __forceinline__ void quant2(float q, int8_t& a1, int8_t& a2) {
    int i1 = __float2int_rn(q);
    int i2 = __float2int_rn((q - (float)i1) * 256.f);
    i2 = i2 < -127 ? -127 : (i2 > 127 ? 127 : i2);
    a1 = (int8_t)i1; a2 = (int8_t)i2;
}

// ==================== prep kernels ====================
// per-row max + 2-limb int8 quantization, fp32 input
__global__ void rowquant_f32(const float* __restrict__ X,
                             int8_t* __restrict__ q1, int8_t* __restrict__ q2,
                             float* __restrict__ sc, int K)
{
    const int r = blockIdx.x, tid = threadIdx.x;
    const float* row = X + (size_t)r * K;
    __shared__ float red[256];
    float m = 0.f;
    for (int i = tid; i < K; i += 256) m = fmaxf(m, fabsf(row[i]));
    red[tid] = m; __syncthreads();
    for (int s = 128; s > 0; s >>= 1) {
        if (tid < s) red[tid] = fmaxf(red[tid], red[tid + s]);
        __syncthreads();
    }
    m = fmaxf(red[0], 1e-30f);
    const float inv = 127.f / m;
    if (tid == 0) sc[r] = m * (1.f / 127.f);
    for (int i = tid; i < K; i += 256) {
        int8_t a1, a2;
        quant2(row[i] * inv, a1, a2);
        q1[(size_t)r * K + i] = a1;
        q2[(size_t)r * K + i] = a2;
    }
}
// same, input = bf16 hi/lo pair (attention output)
__global__ void rowquant_hl(const bf16* __restrict__ Xh, const bf16* __restrict__ Xl,
                            int8_t* __restrict__ q1, int8_t* __restrict__ q2,
                            float* __restrict__ sc, int K)
{
    const int r = blockIdx.x, tid = threadIdx.x;
    const size_t base = (size_t)r * K;
    __shared__ float red[256];
    float m = 0.f;
    for (int i = tid; i < K; i += 256)
        m = fmaxf(m, fabsf(__bfloat162float(Xh[base + i]) + __bfloat162float(Xl[base + i])));
    red[tid] = m; __syncthreads();
    for (int s = 128; s > 0; s >>= 1) {
        if (tid < s) red[tid] = fmaxf(red[tid], red[tid + s]);
        __syncthreads();
    }
    m = fmaxf(red[0], 1e-30f);
    const float inv = 127.f / m;
    if (tid == 0) sc[r] = m * (1.f / 127.f);
    for (int i = tid; i < K; i += 256) {
        float v = __bfloat162float(Xh[base + i]) + __bfloat162float(Xl[base + i]);
        int8_t a1, a2;
        quant2(v * inv, a1, a2);
        q1[base + i] = a1;
        q2[base + i] = a2;
    }
}
// column max of W(K,N), 8 k-segments
__global__ void colmax_part(const float* __restrict__ W, float* __restrict__ part,
                            int K, int N)
{
    const int n = blockIdx.x * 256 + threadIdx.x;
    const int seg = blockIdx.y;
    const int kseg = K / 8;
    const int k0 = seg * kseg;
    float m = 0.f;
    for (int k = k0; k < k0 + kseg; ++k) m = fmaxf(m, fabsf(W[(size_t)k * N + n]));
    part[(size_t)seg * N + n] = m;
}
__global__ void colmax_fin(const float* __restrict__ part, float* __restrict__ sc, int N)
{
    const int n = blockIdx.x * 256 + threadIdx.x;
    if (n >= N) return;
    float m = 0.f;
#pragma unroll
    for (int s = 0; s < 8; ++s) m = fmaxf(m, part[(size_t)s * N + n]);
    sc[n] = fmaxf(m, 1e-30f) * (1.f / 127.f);
}
// transpose W(K,N) -> [N][K] and quantize to 2 limbs with per-n scale
__global__ void wquant(const float* __restrict__ W, const float* __restrict__ sc,
                       int8_t* __restrict__ q1, int8_t* __restrict__ q2, int K, int N)
{
    __shared__ float t[32][33];
    const int tx = threadIdx.x & 31, ty = threadIdx.x >> 5;
    const int bn = blockIdx.x * 32, bk = blockIdx.y * 32;
#pragma unroll
    for (int j = 0; j < 4; ++j)
        t[ty + j * 8][tx] = W[(size_t)(bk + ty + j * 8) * N + bn + tx];
    __syncthreads();
#pragma unroll
    for (int j = 0; j < 4; ++j) {
        const int n = bn + ty + j * 8;
        const int k = bk + tx;
        const float inv = 1.f / sc[n];   // = 127/max
        int8_t a1, a2;
        quant2(t[tx][ty + j * 8] * inv * (1.f / 127.f) * 127.f, a1, a2);  // q = w/sc
        q1[(size_t)n * K + k] = a1;
        q2[(size_t)n * K + k] = a2;
    }
}

// ==================== int8 Ozaki GEMM (m16n8k32, 128x64 tile, occ 2) ====
// C = sA_r * sB_n * (acc11 + (acc12 + acc21)/256) + bias
#define QSTR    80
#define QA_SZ   10240                     // 128 rows * 80 B
#define QB_SZ   5120                      // 64 rows * 80 B
#define Q_B     (2 * QA_SZ)               // 20480
#define Q_STAGE (2 * QA_SZ + 2 * QB_SZ)   // 30720
#define Q_SMEM  (2 * Q_STAGE)             // 61440

__device__ __forceinline__ void qgemm_issue(
    uint32_t sb, int tid, const int8_t* A1, const int8_t* A2,
    const int8_t* B1, const int8_t* B2, int m0, int n0, int kc, int K)
{
#pragma unroll
    for (int i = 0; i < 6; ++i) {
        const int idx = i * 256 + tid;        // 0..1535
        uint32_t dst; const int8_t* src; int grow, seg;
        if (idx < 1024) {                     // A limbs: 2 x 512 (128 rows x 4 segs)
            const int limb = idx >> 9, rem = idx & 511;
            const int row = rem >> 2; seg = rem & 3;
            src = limb ? A2 : A1; grow = m0 + row;
            dst = sb + limb * QA_SZ + (uint32_t)(row * QSTR + seg * 16);
        } else {                              // B limbs: 2 x 256 (64 rows x 4 segs)
            const int j = idx - 1024;
            const int limb = j >> 8, rem = j & 255;
            const int row = rem >> 2; seg = rem & 3;
            src = limb ? B2 : B1; grow = n0 + row;
            dst = sb + Q_B + limb * QB_SZ + (uint32_t)(row * QSTR + seg * 16);
        }
        cp_async16(dst, src + (size_t)grow * K + kc + seg * 16);
    }
    cp_commit();
}

template <int MODE>
__global__ __launch_bounds__(256, 2)
void gemm_i8(const int8_t* __restrict__ A1, const int8_t* __restrict__ A2,
             const int8_t* __restrict__ B1, const int8_t* __restrict__ B2,
             const float* __restrict__ sA, const float* __restrict__ sB,
             const float* __restrict__ bias, float* __restrict__ out,
             int N, int K)
{
    extern __shared__ char smc[];
    const uint32_t base = smem_u32(smc);

    const int tid = threadIdx.x, lane = tid & 31, wid = tid >> 5;
    const int wm = wid & 3, wn = wid >> 2;        // 4m x 2n
    const int m0 = blockIdx.y * 128, n0 = blockIdx.x * 64;

    int acc[2][4][4], accx[2][4][4];
#pragma unroll
    for (int t = 0; t < 2; ++t)
#pragma unroll
        for (int n = 0; n < 4; ++n)
#pragma unroll
            for (int j = 0; j < 4; ++j) { acc[t][n][j] = 0; accx[t][n][j] = 0; }

    const int a_r   = lane & 15;
    const int a_c16 = (lane >> 4) * 16;           // byte offset
    const int b_r   = (lane & 7) + ((lane >> 4) << 3);
    const int b_c16 = ((lane >> 3) & 1) * 16;

    const int NC = K / 64;                        // 12
    qgemm_issue(base, tid, A1, A2, B1, B2, m0, n0, 0, K);

    for (int c = 0; c < NC; ++c) {
        const int buf = c & 1;
        if (c + 1 < NC) {
            qgemm_issue(base + (buf ^ 1) * Q_STAGE, tid, A1, A2, B1, B2,
                        m0, n0, (c + 1) * 64, K);
            cp_wait<1>();
        } else {
            cp_wait<0>();
        }
        __syncthreads();

        const uint32_t sb = base + buf * Q_STAGE;
#pragma unroll
        for (int kf = 0; kf < 2; ++kf) {          // 2 x k32 per 64-chunk
            uint32_t a1f[2][4], a2f[2][4], b1f[2][4], b2f[2][4];
#pragma unroll
            for (int t = 0; t < 2; ++t) {
                const uint32_t off =
                    (uint32_t)((wm * 32 + t * 16 + a_r) * QSTR + kf * 32 + a_c16);
                ldsm_x4(a1f[t], sb + off);
                ldsm_x4(a2f[t], sb + QA_SZ + off);
            }
#pragma unroll
            for (int nt2 = 0; nt2 < 2; ++nt2) {
                const uint32_t off = Q_B +
                    (uint32_t)((wn * 32 + nt2 * 16 + b_r) * QSTR + kf * 32 + b_c16);
                ldsm_x4(b1f[nt2], sb + off);
                ldsm_x4(b2f[nt2], sb + QB_SZ + off);
            }
            // pass 1: a1*b1 (main)
#pragma unroll
            for (int t = 0; t < 2; ++t)
#pragma unroll
                for (int nt2 = 0; nt2 < 2; ++nt2)
#pragma unroll
                    for (int h = 0; h < 2; ++h)
                        imma16832(acc[t][nt2 * 2 + h], a1f[t], b1f[nt2] + h * 2);
            // pass 2: a1*b2 (cross)
#pragma unroll
            for (int t = 0; t < 2; ++t)
#pragma unroll
                for (int nt2 = 0; nt2 < 2; ++nt2)
#pragma unroll
                    for (int h = 0; h < 2; ++h)
                        imma16832(accx[t][nt2 * 2 + h], a1f[t], b2f[nt2] + h * 2);
            // pass 3: a2*b1 (cross)
#pragma unroll
            for (int t = 0; t < 2; ++t)
#pragma unroll
                for (int nt2 = 0; nt2 < 2; ++nt2)
#pragma unroll
                    for (int h = 0; h < 2; ++h)
                        imma16832(accx[t][nt2 * 2 + h], a2f[t], b1f[nt2] + h * 2);
        }
        __syncthreads();
    }

    // epilogue
#pragma unroll
    for (int t = 0; t < 2; ++t) {
        const int gr0 = m0 + wm * 32 + t * 16 + (lane >> 2);
        const float sa0 = sA[gr0], sa1 = sA[gr0 + 8];
#pragma unroll
        for (int nt = 0; nt < 4; ++nt) {
            const int gn = n0 + wn * 32 + nt * 8 + 2 * (lane & 3);
            const float sb0 = sB[gn], sb1 = sB[gn + 1];
            const float b0 = bias[gn], b1 = bias[gn + 1];
            const float v00 = sa0 * sb0 * ((float)acc[t][nt][0] + (float)accx[t][nt][0] * (1.f / 256.f)) + b0;
            const float v01 = sa0 * sb1 * ((float)acc[t][nt][1] + (float)accx[t][nt][1] * (1.f / 256.f)) + b1;
            const float v10 = sa1 * sb0 * ((float)acc[t][nt][2] + (float)accx[t][nt][2] * (1.f / 256.f)) + b0;
            const float v11 = sa1 * sb1 * ((float)acc[t][nt][3] + (float)accx[t][nt][3] * (1.f / 256.f)) + b1;
            if (MODE == 0) {
                *(float2*)&out[(size_t)gr0 * N + gn]       = make_float2(v00, v01);
                *(float2*)&out[(size_t)(gr0 + 8) * N + gn] = make_float2(v10, v11);
            } else {
                const int part = gn / DMODEL;
                const int w = gn % DMODEL;
                const int hh = w >> 6, dd = w & 63;
                bf16* dh = (part == 0) ? g_qh : (part == 1) ? g_kh : g_vh;
                bf16* dl = (part == 0) ? g_ql : (part == 1) ? g_kl : g_vl;
                const int bb = gr0 >> 11;
                const int ll0 = gr0 & 2047;
                const size_t i0 = (((size_t)bb * NHEADS + hh) * SEQLEN + ll0) * DK + dd;
                const size_t i1 = i0 + 8 * DK;
                uint32_t ph, pl;
                split2(v00, v01, ph, pl);
                *(uint32_t*)(dh + i0) = ph; *(uint32_t*)(dl + i0) = pl;
                split2(v10, v11, ph, pl);
                *(uint32_t*)(dh + i1) = ph; *(uint32_t*)(dl + i1) = pl;
            }
        }
    }
}

// ==================== flash attention via mma.sync (bf16x3, occ 2) ======
// (unchanged from R10 best config)
#define GSTR 72
#define KV_STAGE  36864
#define ATT_MASK  110592
#define ATT_SMEM  (110592 + 512)
#define SCALE_L2E 0.1803368867f           // 0.125 * log2(e)

__device__ __forceinline__ void attn_issue_kv(
    uint32_t base, int tid, const bf16* Kh, const bf16* Kl,
    const bf16* Vh, const bf16* Vl, const int* amask_row, int kb, int buf)
{
    const uint32_t sb = base + 36864 + buf * KV_STAGE;
#pragma unroll
    for (int i = 0; i < 8; ++i) {
        const int idx = i * 256 + tid;      // 4 arrays x 512
        const int arr = idx >> 9;
        const int rem = idx & 511;
        const int row = rem >> 3, seg = rem & 7;
        const bf16* src = (arr == 0) ? Kh : (arr == 1) ? Kl : (arr == 2) ? Vh : Vl;
        cp_async16(sb + arr * 9216 + (uint32_t)(row * GSTR + seg * 8) * 2,
                   src + (size_t)(kb + row) * DK + seg * 8);
    }
    if (tid < 16)
        cp_async16(base + ATT_MASK + buf * 256 + tid * 16, amask_row + kb + tid * 4);
    cp_commit();
}

__global__ __launch_bounds__(256, 2)
void attn_mma(const int* __restrict__ amask)
{
    extern __shared__ char smc[];
    const uint32_t base = smem_u32(smc);

    const int tid = threadIdx.x, lane = tid & 31, wid = tid >> 5;
    const int bh = blockIdx.y, b = bh / NHEADS, h = bh % NHEADS;
    const int qb = blockIdx.x * 128;

    const bf16* Qh = g_qh + (size_t)bh * SEQLEN * DK;
    const bf16* Ql = g_ql + (size_t)bh * SEQLEN * DK;
    const bf16* Kh = g_kh + (size_t)bh * SEQLEN * DK;
    const bf16* Kl = g_kl + (size_t)bh * SEQLEN * DK;
    const bf16* Vh = g_vh + (size_t)bh * SEQLEN * DK;
    const bf16* Vl = g_vl + (size_t)bh * SEQLEN * DK;
    const int* amask_row = amask + (size_t)b * SEQLEN;

#pragma unroll
    for (int i = 0; i < 8; ++i) {
        const int idx = i * 256 + tid;
        const int arr = idx >> 10;
        const int rem = idx & 1023;
        const int row = rem >> 3, seg = rem & 7;
        const bf16* src = arr ? Ql : Qh;
        cp_async16(base + arr * 18432 + (uint32_t)(row * GSTR + seg * 8) * 2,
                   src + (size_t)(qb + row) * DK + seg * 8);
    }
    attn_issue_kv(base, tid, Kh, Kl, Vh, Vl, amask_row, 0, 0);

    float m0s = -1e30f, m1s = -1e30f, l0s = 0.f, l1s = 0.f;
    float oacc[8][4];
#pragma unroll
    for (int n = 0; n < 8; ++n)
#pragma unroll
        for (int j = 0; j < 4; ++j) oacc[n][j] = 0.f;

    const int a_r  = lane & 15;
    const int a_c8 = (lane >> 4) * 8;
    const int kb_r = (lane & 7) + ((lane >> 4) << 3);
    const int kb_c8 = ((lane >> 3) & 1) * 8;
    const int vb_r = (lane & 7) + ((lane >> 3) & 1) * 8;
    const int vb_c8 = (lane >> 4) * 8;
    const int mrow = wid * 16;
    const int cbase = 2 * (lane & 3);

    const int NIT = SEQLEN / 64;   // 32
    for (int it = 0; it < NIT; ++it) {
        const int buf = it & 1;
        if (it + 1 < NIT) {
            attn_issue_kv(base, tid, Kh, Kl, Vh, Vl, amask_row, (it + 1) * 64, buf ^ 1);
            cp_wait<1>();
        } else {
            cp_wait<0>();
        }
        __syncthreads();

        const uint32_t kvb = base + 36864 + buf * KV_STAGE;
        const int* smask = (const int*)(smc + ATT_MASK + buf * 256);

        float sacc[8][4];
#pragma unroll
        for (int n = 0; n < 8; ++n)
#pragma unroll
            for (int j = 0; j < 4; ++j) sacc[n][j] = 0.f;

#pragma unroll
        for (int kf = 0; kf < 4; ++kf) {
            uint32_t qh4[4], ql4[4];
            const uint32_t qoff = (uint32_t)((mrow + a_r) * GSTR + kf * 16 + a_c8) * 2;
            ldsm_x4(qh4, base + qoff);
            ldsm_x4(ql4, base + 18432 + qoff);
#pragma unroll
            for (int np = 0; np < 2; ++np) {
                uint32_t kh4[2][4], kl4[2][4];
#pragma unroll
                for (int j = 0; j < 2; ++j) {
                    const int nt2 = np * 2 + j;
                    const uint32_t koff =
                        (uint32_t)((nt2 * 16 + kb_r) * GSTR + kf * 16 + kb_c8) * 2;
                    ldsm_x4(kh4[j], kvb + koff);
                    ldsm_x4(kl4[j], kvb + 9216 + koff);
                }
                float* d[4] = {sacc[np * 4 + 0], sacc[np * 4 + 1],
                               sacc[np * 4 + 2], sacc[np * 4 + 3]};
#pragma unroll
                for (int j = 0; j < 2; ++j)
#pragma unroll
                    for (int hh = 0; hh < 2; ++hh)
                        mma16816(d[j * 2 + hh], qh4, kh4[j] + hh * 2);
#pragma unroll
                for (int j = 0; j < 2; ++j)
#pragma unroll
                    for (int hh = 0; hh < 2; ++hh)
                        mma16816(d[j * 2 + hh], qh4, kl4[j] + hh * 2);
#pragma unroll
                for (int j = 0; j < 2; ++j)
#pragma unroll
                    for (int hh = 0; hh < 2; ++hh)
                        mma16816(d[j * 2 + hh], ql4, kh4[j] + hh * 2);
            }
        }

#pragma unroll
        for (int nt = 0; nt < 8; ++nt) {
            const float ma = smask[nt * 8 + cbase]     ? 0.f : -1e30f;
            const float mb = smask[nt * 8 + cbase + 1] ? 0.f : -1e30f;
            sacc[nt][0] = sacc[nt][0] * SCALE_L2E + ma;
            sacc[nt][1] = sacc[nt][1] * SCALE_L2E + mb;
            sacc[nt][2] = sacc[nt][2] * SCALE_L2E + ma;
            sacc[nt][3] = sacc[nt][3] * SCALE_L2E + mb;
        }

        float mx0 = -1e30f, mx1 = -1e30f;
#pragma unroll
        for (int nt = 0; nt < 8; ++nt) {
            mx0 = fmaxf(mx0, fmaxf(sacc[nt][0], sacc[nt][1]));
            mx1 = fmaxf(mx1, fmaxf(sacc[nt][2], sacc[nt][3]));
        }
        mx0 = fmaxf(mx0, __shfl_xor_sync(0xffffffffu, mx0, 1));
        mx0 = fmaxf(mx0, __shfl_xor_sync(0xffffffffu, mx0, 2));
        mx1 = fmaxf(mx1, __shfl_xor_sync(0xffffffffu, mx1, 1));
        mx1 = fmaxf(mx1, __shfl_xor_sync(0xffffffffu, mx1, 2));
        const float mn0 = fmaxf(m0s, mx0), mn1 = fmaxf(m1s, mx1);
        const float al0 = exp2f(m0s - mn0), al1 = exp2f(m1s - mn1);
        m0s = mn0; m1s = mn1;

        float rs0 = 0.f, rs1 = 0.f;
#pragma unroll
        for (int nt = 0; nt < 8; ++nt) {
            sacc[nt][0] = exp2f(sacc[nt][0] - mn0);
            sacc[nt][1] = exp2f(sacc[nt][1] - mn0);
            sacc[nt][2] = exp2f(sacc[nt][2] - mn1);
            sacc[nt][3] = exp2f(sacc[nt][3] - mn1);
            rs0 += sacc[nt][0] + sacc[nt][1];
            rs1 += sacc[nt][2] + sacc[nt][3];
        }
        rs0 += __shfl_xor_sync(0xffffffffu, rs0, 1);
        rs0 += __shfl_xor_sync(0xffffffffu, rs0, 2);
        rs1 += __shfl_xor_sync(0xffffffffu, rs1, 1);
        rs1 += __shfl_xor_sync(0xffffffffu, rs1, 2);
        l0s = l0s * al0 + rs0;
        l1s = l1s * al1 + rs1;
#pragma unroll
        for (int nt = 0; nt < 8; ++nt) {
            oacc[nt][0] *= al0; oacc[nt][1] *= al0;
            oacc[nt][2] *= al1; oacc[nt][3] *= al1;
        }

#pragma unroll
        for (int kf2 = 0; kf2 < 4; ++kf2) {
            uint32_t ph4[4], pl4[4];
            split2(sacc[2 * kf2][0],     sacc[2 * kf2][1],     ph4[0], pl4[0]);
            split2(sacc[2 * kf2][2],     sacc[2 * kf2][3],     ph4[1], pl4[1]);
            split2(sacc[2 * kf2 + 1][0], sacc[2 * kf2 + 1][1], ph4[2], pl4[2]);
            split2(sacc[2 * kf2 + 1][2], sacc[2 * kf2 + 1][3], ph4[3], pl4[3]);
#pragma unroll
            for (int dp = 0; dp < 2; ++dp) {
                uint32_t vh4[2][4], vl4[2][4];
#pragma unroll
                for (int j = 0; j < 2; ++j) {
                    const int dt2 = dp * 2 + j;
                    const uint32_t voff =
                        (uint32_t)((kf2 * 16 + vb_r) * GSTR + dt2 * 16 + vb_c8) * 2;
                    ldsm_x4t(vh4[j], kvb + 18432 + voff);
                    ldsm_x4t(vl4[j], kvb + 27648 + voff);
                }
                float* d[4] = {oacc[dp * 4 + 0], oacc[dp * 4 + 1],
                               oacc[dp * 4 + 2], oacc[dp * 4 + 3]};
#pragma unroll
                for (int j = 0; j < 2; ++j)
#pragma unroll
                    for (int hh = 0; hh < 2; ++hh)
                        mma16816(d[j * 2 + hh], ph4, vh4[j] + hh * 2);
#pragma unroll
                for (int j = 0; j < 2; ++j)
#pragma unroll
                    for (int hh = 0; hh < 2; ++hh)
                        mma16816(d[j * 2 + hh], ph4, vl4[j] + hh * 2);
#pragma unroll
                for (int j = 0; j < 2; ++j)
#pragma unroll
                    for (int hh = 0; hh < 2; ++hh)
                        mma16816(d[j * 2 + hh], pl4, vh4[j] + hh * 2);
            }
        }
        __syncthreads();
    }

    const float inv0 = 1.f / l0s, inv1 = 1.f / l1s;
    const int row0 = qb + mrow + (lane >> 2);
#pragma unroll
    for (int dt = 0; dt < 8; ++dt) {
        const int col = h * DK + dt * 8 + 2 * (lane & 3);
        const size_t i0 = ((size_t)b * SEQLEN + row0) * DMODEL + col;
        const size_t i1 = i0 + (size_t)8 * DMODEL;
        uint32_t hh, ll;
        split2(oacc[dt][0] * inv0, oacc[dt][1] * inv0, hh, ll);
        *(uint32_t*)(g_ohi + i0) = hh; *(uint32_t*)(g_olo + i0) = ll;
        split2(oacc[dt][2] * inv1, oacc[dt][3] * inv1, hh, ll);
        *(uint32_t*)(g_ohi + i1) = hh; *(uint32_t*)(g_olo + i1) = ll;
    }
}

// ==================== launch ====================
extern "C" void kernel_launch(void* const* d_in, const int* in_sizes, int n_in,
                              void* d_out, int out_size)
{
    const float* x     = (const float*)d_in[0];
    const int*   amask = (const int*)  d_in[1];
    const float* w_qkv = (const float*)d_in[2];
    const float* b_qkv = (const float*)d_in[3];
    const float* w_out = (const float*)d_in[4];
    const float* b_out = (const float*)d_in[5];
    float*       out   = (float*)d_out;

    int8_t *qx1, *qx2, *qo1, *qo2, *qwq1, *qwq2, *qwo1, *qwo2;
    float *sx, *so, *swq, *swo, *pm;
    bf16 *ohi, *olo;
    cudaGetSymbolAddress((void**)&qx1, g_qx1);
    cudaGetSymbolAddress((void**)&qx2, g_qx2);
    cudaGetSymbolAddress((void**)&qo1, g_qo1);
    cudaGetSymbolAddress((void**)&qo2, g_qo2);
    cudaGetSymbolAddress((void**)&qwq1, g_qwq1);
    cudaGetSymbolAddress((void**)&qwq2, g_qwq2);
    cudaGetSymbolAddress((void**)&qwo1, g_qwo1);
    cudaGetSymbolAddress((void**)&qwo2, g_qwo2);
    cudaGetSymbolAddress((void**)&sx, g_sx);
    cudaGetSymbolAddress((void**)&so, g_so);
    cudaGetSymbolAddress((void**)&swq, g_swq);
    cudaGetSymbolAddress((void**)&swo, g_swo);
    cudaGetSymbolAddress((void**)&pm, g_pm);
    cudaGetSymbolAddress((void**)&ohi, g_ohi);
    cudaGetSymbolAddress((void**)&olo, g_olo);

    // 0) quantization prep
    rowquant_f32<<<MTOT, 256>>>(x, qx1, qx2, sx, DMODEL);
    colmax_part<<<dim3(3 * DMODEL / 256, 8), 256>>>(w_qkv, pm, DMODEL, 3 * DMODEL);
    colmax_fin<<<3 * DMODEL / 256, 256>>>(pm, swq, 3 * DMODEL);
    wquant<<<dim3(3 * DMODEL / 32, DMODEL / 32), 256>>>(w_qkv, swq, qwq1, qwq2, DMODEL, 3 * DMODEL);
    colmax_part<<<dim3(DMODEL / 256, 8), 256>>>(w_out, pm, DMODEL, DMODEL);
    colmax_fin<<<DMODEL / 256, 256>>>(pm, swo, DMODEL);
    wquant<<<dim3(DMODEL / 32, DMODEL / 32), 256>>>(w_out, swo, qwo1, qwo2, DMODEL, DMODEL);

    // 1) QKV projection (int8 Ozaki, 128x64 tiles, occ 2)
    cudaFuncSetAttribute(gemm_i8<1>, cudaFuncAttributeMaxDynamicSharedMemorySize, Q_SMEM);
    gemm_i8<1><<<dim3(3 * DMODEL / 64, MTOT / 128), 256, Q_SMEM>>>(
        qx1, qx2, qwq1, qwq2, sx, swq, b_qkv, nullptr, 3 * DMODEL, DMODEL);

    // 2) flash attention (bf16x3, occ 2)
    cudaFuncSetAttribute(attn_mma, cudaFuncAttributeMaxDynamicSharedMemorySize, ATT_SMEM);
    attn_mma<<<dim3(SEQLEN / 128, BATCH * NHEADS), 256, ATT_SMEM>>>(amask);

    // 3) quantize attention output, then out-projection (int8 Ozaki)
    rowquant_hl<<<MTOT, 256>>>(ohi, olo, qo1, qo2, so, DMODEL);
    cudaFuncSetAttribute(gemm_i8<0>, cudaFuncAttributeMaxDynamicSharedMemorySize, Q_SMEM);
    gemm_i8<0><<<dim3(DMODEL / 64, MTOT / 128), 256, Q_SMEM>>>(
        qo1, qo2, qwo1, qwo2, so, swo, b_out, out, DMODEL, DMODEL);
}

// round 12
// speedup vs baseline: 2.3585x; 2.3585x over previous
#include <cuda_runtime.h>
#include <cuda_fp16.h>
#include <cstdint>

#define BATCH   2
#define NHEADS  12
#define SEQLEN  2048
#define DMODEL  768
#define DK      64
#define MTOT    (BATCH * SEQLEN)          // 4096

typedef __half fp16;

// ---------------- scratch (no allocations allowed) ----------------
__device__ __align__(256) fp16 g_x1[(size_t)MTOT * DMODEL];          // x single fp16
__device__ __align__(256) fp16 g_wqh[(size_t)3 * DMODEL * DMODEL];   // W_qkv^T [N][K] hi
__device__ __align__(256) fp16 g_wql[(size_t)3 * DMODEL * DMODEL];   // lo
__device__ __align__(256) fp16 g_woh[(size_t)DMODEL * DMODEL];       // W_out^T [N][K] hi
__device__ __align__(256) fp16 g_wol[(size_t)DMODEL * DMODEL];       // lo
__device__ __align__(256) fp16 g_qs[(size_t)BATCH * NHEADS * SEQLEN * DK];  // Q single
__device__ __align__(256) fp16 g_kh[(size_t)BATCH * NHEADS * SEQLEN * DK];
__device__ __align__(256) fp16 g_kl[(size_t)BATCH * NHEADS * SEQLEN * DK];
__device__ __align__(256) fp16 g_vh[(size_t)BATCH * NHEADS * SEQLEN * DK];
__device__ __align__(256) fp16 g_vl[(size_t)BATCH * NHEADS * SEQLEN * DK];
__device__ __align__(256) fp16 g_os[(size_t)MTOT * DMODEL];          // O single fp16

// ==================== helpers ====================
__device__ __forceinline__ uint32_t smem_u32(const void* p) {
    uint32_t a;
    asm("{ .reg .u64 t; cvta.to.shared.u64 t, %1; cvt.u32.u64 %0, t; }" : "=r"(a) : "l"(p));
    return a;
}
__device__ __forceinline__ void mma16816(float* d, const uint32_t* a, const uint32_t* b) {
    asm volatile(
        "mma.sync.aligned.m16n8k16.row.col.f32.f16.f16.f32 "
        "{%0,%1,%2,%3}, {%4,%5,%6,%7}, {%8,%9}, {%0,%1,%2,%3};"
        : "+f"(d[0]), "+f"(d[1]), "+f"(d[2]), "+f"(d[3])
        : "r"(a[0]), "r"(a[1]), "r"(a[2]), "r"(a[3]), "r"(b[0]), "r"(b[1]));
}
__device__ __forceinline__ void ldsm_x4(uint32_t* r, uint32_t addr) {
    asm volatile("ldmatrix.sync.aligned.m8n8.x4.shared.b16 {%0,%1,%2,%3}, [%4];"
                 : "=r"(r[0]), "=r"(r[1]), "=r"(r[2]), "=r"(r[3]) : "r"(addr));
}
__device__ __forceinline__ void ldsm_x4t(uint32_t* r, uint32_t addr) {
    asm volatile("ldmatrix.sync.aligned.m8n8.x4.trans.shared.b16 {%0,%1,%2,%3}, [%4];"
                 : "=r"(r[0]), "=r"(r[1]), "=r"(r[2]), "=r"(r[3]) : "r"(addr));
}
__device__ __forceinline__ void cp_async16(uint32_t dst, const void* src) {
    asm volatile("cp.async.cg.shared.global [%0], [%1], 16;" :: "r"(dst), "l"(src));
}
__device__ __forceinline__ void cp_commit() {
    asm volatile("cp.async.commit_group;" ::: "memory");
}
template <int N>
__device__ __forceinline__ void cp_wait() {
    asm volatile("cp.async.wait_group %0;" :: "n"(N) : "memory");
}
// pack two floats into fp16x2 (single precision limb)
__device__ __forceinline__ uint32_t pack2h(float x, float y) {
    __half2 hh = __floats2half2_rn(x, y);
    return *reinterpret_cast<uint32_t*>(&hh);
}
// split (x,y) fp32 -> fp16 hi pair + fp16 residual pair
__device__ __forceinline__ void split2h(float x, float y, uint32_t& h, uint32_t& l) {
    __half2 hh = __floats2half2_rn(x, y);
    float rx = x - __half2float(__low2half(hh));
    float ry = y - __half2float(__high2half(hh));
    __half2 ll = __floats2half2_rn(rx, ry);
    h = *reinterpret_cast<uint32_t*>(&hh);
    l = *reinterpret_cast<uint32_t*>(&ll);
}

// ==================== prep kernels ====================
// x fp32 -> single fp16
__global__ void conv_x_kernel(const float* __restrict__ x, fp16* __restrict__ o, int n4)
{
    int i = blockIdx.x * blockDim.x + threadIdx.x;
    if (i >= n4) return;
    float4 v = ((const float4*)x)[i];
    ((uint32_t*)o)[i * 2 + 0] = pack2h(v.x, v.y);
    ((uint32_t*)o)[i * 2 + 1] = pack2h(v.z, v.w);
}
// transpose W(K,N) -> [N][K], split into fp16 hi/lo
__global__ void tsplit_kernel(const float* __restrict__ W,
                              fp16* __restrict__ Th, fp16* __restrict__ Tl,
                              int K, int N)
{
    __shared__ float t[32][33];
    const int tx = threadIdx.x & 31, ty = threadIdx.x >> 5;   // 256 threads
    const int bn = blockIdx.x * 32, bk = blockIdx.y * 32;
#pragma unroll
    for (int j = 0; j < 4; ++j)
        t[ty + j * 8][tx] = W[(size_t)(bk + ty + j * 8) * N + bn + tx];
    __syncthreads();
#pragma unroll
    for (int j = 0; j < 4; ++j) {
        const int n = bn + ty + j * 8;
        const int k = bk + tx;
        const float v = t[tx][ty + j * 8];
        fp16 h = __float2half_rn(v);
        fp16 l = __float2half_rn(v - __half2float(h));
        Th[(size_t)n * K + k] = h;
        Tl[(size_t)n * K + k] = l;
    }
}

// ==================== fp16x2 GEMM (128x64 tile, occ 2) ====================
// C(M,N) = A(M,K) @ (Bh+Bl)(N,K)^T + bias; A single fp16, B 2-limb fp16.
#define GSTR 72
#define G_A   18432                       // 128 rows * 144 B
#define G_B   9216                        // 64 rows * 144 B
#define G_STAGE (G_A + 2 * G_B)           // 36864
#define G_SMEM  (2 * G_STAGE)             // 73728

__device__ __forceinline__ void gemm_issue(
    uint32_t sb, int tid, const fp16* A1,
    const fp16* Bh, const fp16* Bl, int m0, int n0, int kc, int K)
{
#pragma unroll
    for (int i = 0; i < 8; ++i) {
        const int idx = i * 256 + tid;       // 0..2047
        uint32_t dst; const fp16* src; int grow, seg;
        if (idx < 1024) {                    // A: 128 rows x 8 segs
            const int row = idx >> 3; seg = idx & 7;
            src = A1; grow = m0 + row;
            dst = sb + (uint32_t)(row * GSTR + seg * 8) * 2;
        } else {                             // B hi/lo: 2 arrays x 512
            const int j = idx - 1024;
            const int arr = j >> 9, rem = j & 511;
            const int row = rem >> 3; seg = rem & 7;
            src = arr ? Bl : Bh; grow = n0 + row;
            dst = sb + G_A + arr * G_B + (uint32_t)(row * GSTR + seg * 8) * 2;
        }
        cp_async16(dst, src + (size_t)grow * K + kc + seg * 8);
    }
    cp_commit();
}

template <int MODE>
__global__ __launch_bounds__(256, 2)
void gemm_mma(const fp16* __restrict__ A1,
              const fp16* __restrict__ Bh, const fp16* __restrict__ Bl,
              const float* __restrict__ bias, float* __restrict__ out,
              int N, int K)
{
    extern __shared__ char smc[];
    const uint32_t base = smem_u32(smc);

    const int tid = threadIdx.x, lane = tid & 31, wid = tid >> 5;
    const int wm = wid & 3, wn = wid >> 2;        // 4m x 2n
    const int m0 = blockIdx.y * 128, n0 = blockIdx.x * 64;

    float acc[2][4][4];
#pragma unroll
    for (int t = 0; t < 2; ++t)
#pragma unroll
        for (int n = 0; n < 4; ++n)
#pragma unroll
            for (int j = 0; j < 4; ++j) acc[t][n][j] = 0.f;

    const int a_r  = lane & 15;
    const int a_c8 = (lane >> 4) * 8;
    const int b_r  = (lane & 7) + ((lane >> 4) << 3);
    const int b_c8 = ((lane >> 3) & 1) * 8;

    const int NC = K / 64;                  // 12
    gemm_issue(base, tid, A1, Bh, Bl, m0, n0, 0, K);

    for (int c = 0; c < NC; ++c) {
        const int buf = c & 1;
        if (c + 1 < NC) {
            gemm_issue(base + (buf ^ 1) * G_STAGE, tid, A1, Bh, Bl,
                       m0, n0, (c + 1) * 64, K);
            cp_wait<1>();
        } else {
            cp_wait<0>();
        }
        __syncthreads();

        const uint32_t sb = base + buf * G_STAGE;
#pragma unroll
        for (int kf = 0; kf < 4; ++kf) {
            uint32_t af[2][4], bhf[2][4], blf[2][4];
#pragma unroll
            for (int t = 0; t < 2; ++t) {
                const uint32_t off =
                    (uint32_t)((wm * 32 + t * 16 + a_r) * GSTR + kf * 16 + a_c8) * 2;
                ldsm_x4(af[t], sb + off);
            }
#pragma unroll
            for (int nt2 = 0; nt2 < 2; ++nt2) {
                const uint32_t off = G_A +
                    (uint32_t)((wn * 32 + nt2 * 16 + b_r) * GSTR + kf * 16 + b_c8) * 2;
                ldsm_x4(bhf[nt2], sb + off);
                ldsm_x4(blf[nt2], sb + G_B + off);
            }
            // pass 1: a*bh (8 independent accumulators)
#pragma unroll
            for (int t = 0; t < 2; ++t)
#pragma unroll
                for (int nt2 = 0; nt2 < 2; ++nt2)
#pragma unroll
                    for (int h = 0; h < 2; ++h)
                        mma16816(acc[t][nt2 * 2 + h], af[t], bhf[nt2] + h * 2);
            // pass 2: a*bl
#pragma unroll
            for (int t = 0; t < 2; ++t)
#pragma unroll
                for (int nt2 = 0; nt2 < 2; ++nt2)
#pragma unroll
                    for (int h = 0; h < 2; ++h)
                        mma16816(acc[t][nt2 * 2 + h], af[t], blf[nt2] + h * 2);
        }
        __syncthreads();
    }

    // epilogue
#pragma unroll
    for (int t = 0; t < 2; ++t) {
        const int gr0 = m0 + wm * 32 + t * 16 + (lane >> 2);
#pragma unroll
        for (int nt = 0; nt < 4; ++nt) {
            const int gn = n0 + wn * 32 + nt * 8 + 2 * (lane & 3);
            const float b0 = bias[gn], b1 = bias[gn + 1];
            const float v00 = acc[t][nt][0] + b0, v01 = acc[t][nt][1] + b1;
            const float v10 = acc[t][nt][2] + b0, v11 = acc[t][nt][3] + b1;
            if (MODE == 0) {
                *(float2*)&out[(size_t)gr0 * N + gn]       = make_float2(v00, v01);
                *(float2*)&out[(size_t)(gr0 + 8) * N + gn] = make_float2(v10, v11);
            } else {
                const int part = gn / DMODEL;
                const int w = gn % DMODEL;
                const int hh = w >> 6, dd = w & 63;
                const int bb = gr0 >> 11;
                const int ll0 = gr0 & 2047;
                const size_t i0 = (((size_t)bb * NHEADS + hh) * SEQLEN + ll0) * DK + dd;
                const size_t i1 = i0 + 8 * DK;
                if (part == 0) {                      // Q single fp16
                    *(uint32_t*)(g_qs + i0) = pack2h(v00, v01);
                    *(uint32_t*)(g_qs + i1) = pack2h(v10, v11);
                } else {                              // K/V hi+lo
                    fp16* dh = (part == 1) ? g_kh : g_vh;
                    fp16* dl = (part == 1) ? g_kl : g_vl;
                    uint32_t ph, pl;
                    split2h(v00, v01, ph, pl);
                    *(uint32_t*)(dh + i0) = ph; *(uint32_t*)(dl + i0) = pl;
                    split2h(v10, v11, ph, pl);
                    *(uint32_t*)(dh + i1) = ph; *(uint32_t*)(dl + i1) = pl;
                }
            }
        }
    }
}

// ==================== flash attention (fp16x2, occ 2) ====================
// BM=128, BN=64, 256 thr / 8 warps; Q single fp16, K/V 2-limb fp16,
// P single fp16; 2 KV stages, exp2-domain softmax.
#define KV_STG    36864                   // kh 0 | kl 9216 | vh 18432 | vl 27648
#define ATT_Q     0
#define ATT_KV    18432
#define ATT_MASK  (18432 + 2 * KV_STG)    // 92160
#define ATT_SMEM  (ATT_MASK + 512)        // 92672
#define SCALE_L2E 0.1803368867f           // 0.125 * log2(e)

__device__ __forceinline__ void attn_issue_kv(
    uint32_t base, int tid, const fp16* Kh, const fp16* Kl,
    const fp16* Vh, const fp16* Vl, const int* amask_row, int kb, int buf)
{
    const uint32_t sb = base + ATT_KV + buf * KV_STG;
#pragma unroll
    for (int i = 0; i < 8; ++i) {
        const int idx = i * 256 + tid;      // 4 arrays x 512
        const int arr = idx >> 9;
        const int rem = idx & 511;
        const int row = rem >> 3, seg = rem & 7;
        const fp16* src = (arr == 0) ? Kh : (arr == 1) ? Kl : (arr == 2) ? Vh : Vl;
        cp_async16(sb + arr * 9216 + (uint32_t)(row * GSTR + seg * 8) * 2,
                   src + (size_t)(kb + row) * DK + seg * 8);
    }
    if (tid < 16)
        cp_async16(base + ATT_MASK + buf * 256 + tid * 16, amask_row + kb + tid * 4);
    cp_commit();
}

__global__ __launch_bounds__(256, 2)
void attn_mma(const int* __restrict__ amask)
{
    extern __shared__ char smc[];
    const uint32_t base = smem_u32(smc);

    const int tid = threadIdx.x, lane = tid & 31, wid = tid >> 5;
    const int bh = blockIdx.y, b = bh / NHEADS, h = bh % NHEADS;
    const int qb = blockIdx.x * 128;

    const fp16* Qs = g_qs + (size_t)bh * SEQLEN * DK;
    const fp16* Kh = g_kh + (size_t)bh * SEQLEN * DK;
    const fp16* Kl = g_kl + (size_t)bh * SEQLEN * DK;
    const fp16* Vh = g_vh + (size_t)bh * SEQLEN * DK;
    const fp16* Vl = g_vl + (size_t)bh * SEQLEN * DK;
    const int* amask_row = amask + (size_t)b * SEQLEN;

    // prologue G0: Q (single) + KV chunk 0 + mask 0 (one commit)
#pragma unroll
    for (int i = 0; i < 4; ++i) {
        const int idx = i * 256 + tid;          // 0..1023
        const int row = idx >> 3, seg = idx & 7;
        cp_async16(base + ATT_Q + (uint32_t)(row * GSTR + seg * 8) * 2,
                   Qs + (size_t)(qb + row) * DK + seg * 8);
    }
    attn_issue_kv(base, tid, Kh, Kl, Vh, Vl, amask_row, 0, 0);

    float m0s = -1e30f, m1s = -1e30f, l0s = 0.f, l1s = 0.f;
    float oacc[8][4];
#pragma unroll
    for (int n = 0; n < 8; ++n)
#pragma unroll
        for (int j = 0; j < 4; ++j) oacc[n][j] = 0.f;

    const int a_r  = lane & 15;
    const int a_c8 = (lane >> 4) * 8;
    const int kb_r = (lane & 7) + ((lane >> 4) << 3);
    const int kb_c8 = ((lane >> 3) & 1) * 8;
    const int vb_r = (lane & 7) + ((lane >> 3) & 1) * 8;
    const int vb_c8 = (lane >> 4) * 8;
    const int mrow = wid * 16;
    const int cbase = 2 * (lane & 3);

    const int NIT = SEQLEN / 64;   // 32
    for (int it = 0; it < NIT; ++it) {
        const int buf = it & 1;
        if (it + 1 < NIT) {
            attn_issue_kv(base, tid, Kh, Kl, Vh, Vl, amask_row, (it + 1) * 64, buf ^ 1);
            cp_wait<1>();
        } else {
            cp_wait<0>();
        }
        __syncthreads();

        const uint32_t kvb = base + ATT_KV + buf * KV_STG;
        const int* smask = (const int*)(smc + ATT_MASK + buf * 256);

        // ---- S = Q @ K^T (2 products: q*kh + q*kl) ----
        float sacc[8][4];
#pragma unroll
        for (int n = 0; n < 8; ++n)
#pragma unroll
            for (int j = 0; j < 4; ++j) sacc[n][j] = 0.f;

#pragma unroll
        for (int kf = 0; kf < 4; ++kf) {
            uint32_t qf[4];
            const uint32_t qoff = (uint32_t)((mrow + a_r) * GSTR + kf * 16 + a_c8) * 2;
            ldsm_x4(qf, base + ATT_Q + qoff);
#pragma unroll
            for (int np = 0; np < 2; ++np) {             // nt2 pair {2np, 2np+1}
                uint32_t kh4[2][4], kl4[2][4];
#pragma unroll
                for (int j = 0; j < 2; ++j) {
                    const int nt2 = np * 2 + j;
                    const uint32_t koff =
                        (uint32_t)((nt2 * 16 + kb_r) * GSTR + kf * 16 + kb_c8) * 2;
                    ldsm_x4(kh4[j], kvb + koff);
                    ldsm_x4(kl4[j], kvb + 9216 + koff);
                }
                float* d[4] = {sacc[np * 4 + 0], sacc[np * 4 + 1],
                               sacc[np * 4 + 2], sacc[np * 4 + 3]};
#pragma unroll
                for (int j = 0; j < 2; ++j)
#pragma unroll
                    for (int hh = 0; hh < 2; ++hh)
                        mma16816(d[j * 2 + hh], qf, kh4[j] + hh * 2);
#pragma unroll
                for (int j = 0; j < 2; ++j)
#pragma unroll
                    for (int hh = 0; hh < 2; ++hh)
                        mma16816(d[j * 2 + hh], qf, kl4[j] + hh * 2);
            }
        }

        // ---- scale (log2 domain) + mask ----
#pragma unroll
        for (int nt = 0; nt < 8; ++nt) {
            const float ma = smask[nt * 8 + cbase]     ? 0.f : -1e30f;
            const float mb = smask[nt * 8 + cbase + 1] ? 0.f : -1e30f;
            sacc[nt][0] = sacc[nt][0] * SCALE_L2E + ma;
            sacc[nt][1] = sacc[nt][1] * SCALE_L2E + mb;
            sacc[nt][2] = sacc[nt][2] * SCALE_L2E + ma;
            sacc[nt][3] = sacc[nt][3] * SCALE_L2E + mb;
        }

        // ---- online softmax (rows r=lane>>2 and r+8), exp2 in-place ----
        float mx0 = -1e30f, mx1 = -1e30f;
#pragma unroll
        for (int nt = 0; nt < 8; ++nt) {
            mx0 = fmaxf(mx0, fmaxf(sacc[nt][0], sacc[nt][1]));
            mx1 = fmaxf(mx1, fmaxf(sacc[nt][2], sacc[nt][3]));
        }
        mx0 = fmaxf(mx0, __shfl_xor_sync(0xffffffffu, mx0, 1));
        mx0 = fmaxf(mx0, __shfl_xor_sync(0xffffffffu, mx0, 2));
        mx1 = fmaxf(mx1, __shfl_xor_sync(0xffffffffu, mx1, 1));
        mx1 = fmaxf(mx1, __shfl_xor_sync(0xffffffffu, mx1, 2));
        const float mn0 = fmaxf(m0s, mx0), mn1 = fmaxf(m1s, mx1);
        const float al0 = exp2f(m0s - mn0), al1 = exp2f(m1s - mn1);
        m0s = mn0; m1s = mn1;

        float rs0 = 0.f, rs1 = 0.f;
#pragma unroll
        for (int nt = 0; nt < 8; ++nt) {
            sacc[nt][0] = exp2f(sacc[nt][0] - mn0);
            sacc[nt][1] = exp2f(sacc[nt][1] - mn0);
            sacc[nt][2] = exp2f(sacc[nt][2] - mn1);
            sacc[nt][3] = exp2f(sacc[nt][3] - mn1);
            rs0 += sacc[nt][0] + sacc[nt][1];
            rs1 += sacc[nt][2] + sacc[nt][3];
        }
        rs0 += __shfl_xor_sync(0xffffffffu, rs0, 1);
        rs0 += __shfl_xor_sync(0xffffffffu, rs0, 2);
        rs1 += __shfl_xor_sync(0xffffffffu, rs1, 1);
        rs1 += __shfl_xor_sync(0xffffffffu, rs1, 2);
        l0s = l0s * al0 + rs0;
        l1s = l1s * al1 + rs1;
#pragma unroll
        for (int nt = 0; nt < 8; ++nt) {
            oacc[nt][0] *= al0; oacc[nt][1] *= al0;
            oacc[nt][2] *= al1; oacc[nt][3] *= al1;
        }

        // ---- O += P @ V (P single fp16; 2 products: p*vh + p*vl) ----
#pragma unroll
        for (int kf2 = 0; kf2 < 4; ++kf2) {
            uint32_t pf[4];
            pf[0] = pack2h(sacc[2 * kf2][0],     sacc[2 * kf2][1]);
            pf[1] = pack2h(sacc[2 * kf2][2],     sacc[2 * kf2][3]);
            pf[2] = pack2h(sacc[2 * kf2 + 1][0], sacc[2 * kf2 + 1][1]);
            pf[3] = pack2h(sacc[2 * kf2 + 1][2], sacc[2 * kf2 + 1][3]);
#pragma unroll
            for (int dp = 0; dp < 2; ++dp) {             // dt2 pair {2dp, 2dp+1}
                uint32_t vh4[2][4], vl4[2][4];
#pragma unroll
                for (int j = 0; j < 2; ++j) {
                    const int dt2 = dp * 2 + j;
                    const uint32_t voff =
                        (uint32_t)((kf2 * 16 + vb_r) * GSTR + dt2 * 16 + vb_c8) * 2;
                    ldsm_x4t(vh4[j], kvb + 18432 + voff);
                    ldsm_x4t(vl4[j], kvb + 27648 + voff);
                }
                float* d[4] = {oacc[dp * 4 + 0], oacc[dp * 4 + 1],
                               oacc[dp * 4 + 2], oacc[dp * 4 + 3]};
#pragma unroll
                for (int j = 0; j < 2; ++j)
#pragma unroll
                    for (int hh = 0; hh < 2; ++hh)
                        mma16816(d[j * 2 + hh], pf, vh4[j] + hh * 2);
#pragma unroll
                for (int j = 0; j < 2; ++j)
#pragma unroll
                    for (int hh = 0; hh < 2; ++hh)
                        mma16816(d[j * 2 + hh], pf, vl4[j] + hh * 2);
            }
        }
        __syncthreads();   // done reading buf before refill
    }

    // epilogue: O /= l, store single fp16 in (B,L,D)
    const float inv0 = 1.f / l0s, inv1 = 1.f / l1s;
    const int row0 = qb + mrow + (lane >> 2);
#pragma unroll
    for (int dt = 0; dt < 8; ++dt) {
        const int col = h * DK + dt * 8 + 2 * (lane & 3);
        const size_t i0 = ((size_t)b * SEQLEN + row0) * DMODEL + col;
        const size_t i1 = i0 + (size_t)8 * DMODEL;
        *(uint32_t*)(g_os + i0) = pack2h(oacc[dt][0] * inv0, oacc[dt][1] * inv0);
        *(uint32_t*)(g_os + i1) = pack2h(oacc[dt][2] * inv1, oacc[dt][3] * inv1);
    }
}

// ==================== launch ====================
extern "C" void kernel_launch(void* const* d_in, const int* in_sizes, int n_in,
                              void* d_out, int out_size)
{
    const float* x     = (const float*)d_in[0];
    const int*   amask = (const int*)  d_in[1];
    const float* w_qkv = (const float*)d_in[2];
    const float* b_qkv = (const float*)d_in[3];
    const float* w_out = (const float*)d_in[4];
    const float* b_out = (const float*)d_in[5];
    float*       out   = (float*)d_out;

    fp16 *x1, *wqh, *wql, *woh, *wol, *os;
    cudaGetSymbolAddress((void**)&x1,  g_x1);
    cudaGetSymbolAddress((void**)&wqh, g_wqh);
    cudaGetSymbolAddress((void**)&wql, g_wql);
    cudaGetSymbolAddress((void**)&woh, g_woh);
    cudaGetSymbolAddress((void**)&wol, g_wol);
    cudaGetSymbolAddress((void**)&os,  g_os);

    // 0) prep: x -> fp16, W -> transposed fp16 hi/lo
    const int n4 = MTOT * DMODEL / 4;
    conv_x_kernel<<<(n4 + 255) / 256, 256>>>(x, x1, n4);
    tsplit_kernel<<<dim3(3 * DMODEL / 32, DMODEL / 32), 256>>>(w_qkv, wqh, wql, DMODEL, 3 * DMODEL);
    tsplit_kernel<<<dim3(DMODEL / 32, DMODEL / 32), 256>>>(w_out, woh, wol, DMODEL, DMODEL);

    // 1) QKV projection (fp16x2, 128x64 tiles, occ 2)
    cudaFuncSetAttribute(gemm_mma<1>, cudaFuncAttributeMaxDynamicSharedMemorySize, G_SMEM);
    gemm_mma<1><<<dim3(3 * DMODEL / 64, MTOT / 128), 256, G_SMEM>>>(
        x1, wqh, wql, b_qkv, nullptr, 3 * DMODEL, DMODEL);

    // 2) flash attention (fp16x2, occ 2)
    cudaFuncSetAttribute(attn_mma, cudaFuncAttributeMaxDynamicSharedMemorySize, ATT_SMEM);
    attn_mma<<<dim3(SEQLEN / 128, BATCH * NHEADS), 256, ATT_SMEM>>>(amask);

    // 3) output projection (fp16x2)
    cudaFuncSetAttribute(gemm_mma<0>, cudaFuncAttributeMaxDynamicSharedMemorySize, G_SMEM);
    gemm_mma<0><<<dim3(DMODEL / 64, MTOT / 128), 256, G_SMEM>>>(
        os, woh, wol, b_out, out, DMODEL, DMODEL);
}

// round 13
// speedup vs baseline: 3.4839x; 1.4772x over previous
#include <cuda_runtime.h>
#include <cuda_fp16.h>
#include <cstdint>

#define BATCH   2
#define NHEADS  12
#define SEQLEN  2048
#define DMODEL  768
#define DK      64
#define MTOT    (BATCH * SEQLEN)          // 4096

typedef __half fp16;

// ---------------- scratch (no allocations allowed) ----------------
__device__ __align__(256) fp16 g_x1[(size_t)MTOT * DMODEL];          // x fp16
__device__ __align__(256) fp16 g_wq[(size_t)3 * DMODEL * DMODEL];    // W_qkv^T [N][K]
__device__ __align__(256) fp16 g_wo[(size_t)DMODEL * DMODEL];        // W_out^T [N][K]
__device__ __align__(256) fp16 g_qs[(size_t)BATCH * NHEADS * SEQLEN * DK];
__device__ __align__(256) fp16 g_ks[(size_t)BATCH * NHEADS * SEQLEN * DK];
__device__ __align__(256) fp16 g_vs[(size_t)BATCH * NHEADS * SEQLEN * DK];
__device__ __align__(256) fp16 g_os[(size_t)MTOT * DMODEL];          // O fp16

// ==================== helpers ====================
__device__ __forceinline__ uint32_t smem_u32(const void* p) {
    uint32_t a;
    asm("{ .reg .u64 t; cvta.to.shared.u64 t, %1; cvt.u32.u64 %0, t; }" : "=r"(a) : "l"(p));
    return a;
}
__device__ __forceinline__ void mma16816(float* d, const uint32_t* a, const uint32_t* b) {
    asm volatile(
        "mma.sync.aligned.m16n8k16.row.col.f32.f16.f16.f32 "
        "{%0,%1,%2,%3}, {%4,%5,%6,%7}, {%8,%9}, {%0,%1,%2,%3};"
        : "+f"(d[0]), "+f"(d[1]), "+f"(d[2]), "+f"(d[3])
        : "r"(a[0]), "r"(a[1]), "r"(a[2]), "r"(a[3]), "r"(b[0]), "r"(b[1]));
}
__device__ __forceinline__ void ldsm_x4(uint32_t* r, uint32_t addr) {
    asm volatile("ldmatrix.sync.aligned.m8n8.x4.shared.b16 {%0,%1,%2,%3}, [%4];"
                 : "=r"(r[0]), "=r"(r[1]), "=r"(r[2]), "=r"(r[3]) : "r"(addr));
}
__device__ __forceinline__ void ldsm_x4t(uint32_t* r, uint32_t addr) {
    asm volatile("ldmatrix.sync.aligned.m8n8.x4.trans.shared.b16 {%0,%1,%2,%3}, [%4];"
                 : "=r"(r[0]), "=r"(r[1]), "=r"(r[2]), "=r"(r[3]) : "r"(addr));
}
__device__ __forceinline__ void cp_async16(uint32_t dst, const void* src) {
    asm volatile("cp.async.cg.shared.global [%0], [%1], 16;" :: "r"(dst), "l"(src));
}
__device__ __forceinline__ void cp_commit() {
    asm volatile("cp.async.commit_group;" ::: "memory");
}
template <int N>
__device__ __forceinline__ void cp_wait() {
    asm volatile("cp.async.wait_group %0;" :: "n"(N) : "memory");
}
__device__ __forceinline__ uint32_t pack2h(float x, float y) {
    __half2 hh = __floats2half2_rn(x, y);
    return *reinterpret_cast<uint32_t*>(&hh);
}

// ==================== prep kernels ====================
__global__ void conv_x_kernel(const float* __restrict__ x, fp16* __restrict__ o, int n4)
{
    int i = blockIdx.x * blockDim.x + threadIdx.x;
    if (i >= n4) return;
    float4 v = ((const float4*)x)[i];
    ((uint32_t*)o)[i * 2 + 0] = pack2h(v.x, v.y);
    ((uint32_t*)o)[i * 2 + 1] = pack2h(v.z, v.w);
}
// transpose W(K,N) -> [N][K] fp16
__global__ void ttrans_kernel(const float* __restrict__ W, fp16* __restrict__ T,
                              int K, int N)
{
    __shared__ float t[32][33];
    const int tx = threadIdx.x & 31, ty = threadIdx.x >> 5;   // 256 threads
    const int bn = blockIdx.x * 32, bk = blockIdx.y * 32;
#pragma unroll
    for (int j = 0; j < 4; ++j)
        t[ty + j * 8][tx] = W[(size_t)(bk + ty + j * 8) * N + bn + tx];
    __syncthreads();
#pragma unroll
    for (int j = 0; j < 4; ++j) {
        const int n = bn + ty + j * 8;
        const int k = bk + tx;
        T[(size_t)n * K + k] = __float2half_rn(t[tx][ty + j * 8]);
    }
}

// ==================== fp16 GEMM (128x64 tile, occ 2) ====================
// C(M,N) = A(M,K) @ B(N,K)^T + bias, fp32 accum; both operands single fp16.
#define GSTR 72
#define G_A   18432                       // 128 rows * 144 B
#define G_B   9216                        // 64 rows * 144 B
#define G_STAGE (G_A + G_B)               // 27648
#define G_SMEM  (2 * G_STAGE)             // 55296

__device__ __forceinline__ void gemm_issue(
    uint32_t sb, int tid, const fp16* A1, const fp16* B1,
    int m0, int n0, int kc, int K)
{
#pragma unroll
    for (int i = 0; i < 6; ++i) {
        const int idx = i * 256 + tid;       // 0..1535
        uint32_t dst; const fp16* src; int grow, seg;
        if (idx < 1024) {                    // A: 128 rows x 8 segs
            const int row = idx >> 3; seg = idx & 7;
            src = A1; grow = m0 + row;
            dst = sb + (uint32_t)(row * GSTR + seg * 8) * 2;
        } else {                             // B: 64 rows x 8 segs
            const int j = idx - 1024;
            const int row = j >> 3; seg = j & 7;
            src = B1; grow = n0 + row;
            dst = sb + G_A + (uint32_t)(row * GSTR + seg * 8) * 2;
        }
        cp_async16(dst, src + (size_t)grow * K + kc + seg * 8);
    }
    cp_commit();
}

template <int MODE>
__global__ __launch_bounds__(256, 2)
void gemm_mma(const fp16* __restrict__ A1, const fp16* __restrict__ B1,
              const float* __restrict__ bias, float* __restrict__ out,
              int N, int K)
{
    extern __shared__ char smc[];
    const uint32_t base = smem_u32(smc);

    const int tid = threadIdx.x, lane = tid & 31, wid = tid >> 5;
    const int wm = wid & 3, wn = wid >> 2;        // 4m x 2n
    const int m0 = blockIdx.y * 128, n0 = blockIdx.x * 64;

    float acc[2][4][4];
#pragma unroll
    for (int t = 0; t < 2; ++t)
#pragma unroll
        for (int n = 0; n < 4; ++n)
#pragma unroll
            for (int j = 0; j < 4; ++j) acc[t][n][j] = 0.f;

    const int a_r  = lane & 15;
    const int a_c8 = (lane >> 4) * 8;
    const int b_r  = (lane & 7) + ((lane >> 4) << 3);
    const int b_c8 = ((lane >> 3) & 1) * 8;

    const int NC = K / 64;                  // 12
    gemm_issue(base, tid, A1, B1, m0, n0, 0, K);

    for (int c = 0; c < NC; ++c) {
        const int buf = c & 1;
        if (c + 1 < NC) {
            gemm_issue(base + (buf ^ 1) * G_STAGE, tid, A1, B1,
                       m0, n0, (c + 1) * 64, K);
            cp_wait<1>();
        } else {
            cp_wait<0>();
        }
        __syncthreads();

        const uint32_t sb = base + buf * G_STAGE;
#pragma unroll
        for (int kf = 0; kf < 4; ++kf) {
            uint32_t af[2][4], bf[2][4];
#pragma unroll
            for (int t = 0; t < 2; ++t) {
                const uint32_t off =
                    (uint32_t)((wm * 32 + t * 16 + a_r) * GSTR + kf * 16 + a_c8) * 2;
                ldsm_x4(af[t], sb + off);
            }
#pragma unroll
            for (int nt2 = 0; nt2 < 2; ++nt2) {
                const uint32_t off = G_A +
                    (uint32_t)((wn * 32 + nt2 * 16 + b_r) * GSTR + kf * 16 + b_c8) * 2;
                ldsm_x4(bf[nt2], sb + off);
            }
#pragma unroll
            for (int t = 0; t < 2; ++t)
#pragma unroll
                for (int nt2 = 0; nt2 < 2; ++nt2)
#pragma unroll
                    for (int h = 0; h < 2; ++h)
                        mma16816(acc[t][nt2 * 2 + h], af[t], bf[nt2] + h * 2);
        }
        __syncthreads();
    }

    // epilogue
#pragma unroll
    for (int t = 0; t < 2; ++t) {
        const int gr0 = m0 + wm * 32 + t * 16 + (lane >> 2);
#pragma unroll
        for (int nt = 0; nt < 4; ++nt) {
            const int gn = n0 + wn * 32 + nt * 8 + 2 * (lane & 3);
            const float b0 = bias[gn], b1 = bias[gn + 1];
            const float v00 = acc[t][nt][0] + b0, v01 = acc[t][nt][1] + b1;
            const float v10 = acc[t][nt][2] + b0, v11 = acc[t][nt][3] + b1;
            if (MODE == 0) {
                *(float2*)&out[(size_t)gr0 * N + gn]       = make_float2(v00, v01);
                *(float2*)&out[(size_t)(gr0 + 8) * N + gn] = make_float2(v10, v11);
            } else {
                const int part = gn / DMODEL;
                const int w = gn % DMODEL;
                const int hh = w >> 6, dd = w & 63;
                const int bb = gr0 >> 11;
                const int ll0 = gr0 & 2047;
                const size_t i0 = (((size_t)bb * NHEADS + hh) * SEQLEN + ll0) * DK + dd;
                const size_t i1 = i0 + 8 * DK;
                fp16* dst = (part == 0) ? g_qs : (part == 1) ? g_ks : g_vs;
                *(uint32_t*)(dst + i0) = pack2h(v00, v01);
                *(uint32_t*)(dst + i1) = pack2h(v10, v11);
            }
        }
    }
}

// ==================== flash attention (fp16, occ 2) ====================
// BM=128, BN=64, 256 thr / 8 warps; Q/K/V/P all single fp16, fp32 accum.
#define KV_STG    18432                   // k 0 | v 9216
#define ATT_Q     0
#define ATT_KV    18432
#define ATT_MASK  (18432 + 2 * KV_STG)    // 55296
#define ATT_SMEM  (ATT_MASK + 512)        // 55808
#define SCALE_L2E 0.1803368867f           // 0.125 * log2(e)

__device__ __forceinline__ void attn_issue_kv(
    uint32_t base, int tid, const fp16* Ks, const fp16* Vs,
    const int* amask_row, int kb, int buf)
{
    const uint32_t sb = base + ATT_KV + buf * KV_STG;
#pragma unroll
    for (int i = 0; i < 4; ++i) {
        const int idx = i * 256 + tid;      // 2 arrays x 512
        const int arr = idx >> 9;
        const int rem = idx & 511;
        const int row = rem >> 3, seg = rem & 7;
        const fp16* src = arr ? Vs : Ks;
        cp_async16(sb + arr * 9216 + (uint32_t)(row * GSTR + seg * 8) * 2,
                   src + (size_t)(kb + row) * DK + seg * 8);
    }
    if (tid < 16)
        cp_async16(base + ATT_MASK + buf * 256 + tid * 16, amask_row + kb + tid * 4);
    cp_commit();
}

__global__ __launch_bounds__(256, 2)
void attn_mma(const int* __restrict__ amask)
{
    extern __shared__ char smc[];
    const uint32_t base = smem_u32(smc);

    const int tid = threadIdx.x, lane = tid & 31, wid = tid >> 5;
    const int bh = blockIdx.y, b = bh / NHEADS, h = bh % NHEADS;
    const int qb = blockIdx.x * 128;

    const fp16* Qs = g_qs + (size_t)bh * SEQLEN * DK;
    const fp16* Ks = g_ks + (size_t)bh * SEQLEN * DK;
    const fp16* Vs = g_vs + (size_t)bh * SEQLEN * DK;
    const int* amask_row = amask + (size_t)b * SEQLEN;

    // prologue G0: Q + KV chunk 0 + mask 0 (one commit)
#pragma unroll
    for (int i = 0; i < 4; ++i) {
        const int idx = i * 256 + tid;          // 0..1023
        const int row = idx >> 3, seg = idx & 7;
        cp_async16(base + ATT_Q + (uint32_t)(row * GSTR + seg * 8) * 2,
                   Qs + (size_t)(qb + row) * DK + seg * 8);
    }
    attn_issue_kv(base, tid, Ks, Vs, amask_row, 0, 0);

    float m0s = -1e30f, m1s = -1e30f, l0s = 0.f, l1s = 0.f;
    float oacc[8][4];
#pragma unroll
    for (int n = 0; n < 8; ++n)
#pragma unroll
        for (int j = 0; j < 4; ++j) oacc[n][j] = 0.f;

    const int a_r  = lane & 15;
    const int a_c8 = (lane >> 4) * 8;
    const int kb_r = (lane & 7) + ((lane >> 4) << 3);
    const int kb_c8 = ((lane >> 3) & 1) * 8;
    const int vb_r = (lane & 7) + ((lane >> 3) & 1) * 8;
    const int vb_c8 = (lane >> 4) * 8;
    const int mrow = wid * 16;
    const int cbase = 2 * (lane & 3);

    const int NIT = SEQLEN / 64;   // 32
    for (int it = 0; it < NIT; ++it) {
        const int buf = it & 1;
        if (it + 1 < NIT) {
            attn_issue_kv(base, tid, Ks, Vs, amask_row, (it + 1) * 64, buf ^ 1);
            cp_wait<1>();
        } else {
            cp_wait<0>();
        }
        __syncthreads();

        const uint32_t kvb = base + ATT_KV + buf * KV_STG;
        const int* smask = (const int*)(smc + ATT_MASK + buf * 256);

        // ---- S = Q @ K^T ----
        float sacc[8][4];
#pragma unroll
        for (int n = 0; n < 8; ++n)
#pragma unroll
            for (int j = 0; j < 4; ++j) sacc[n][j] = 0.f;

#pragma unroll
        for (int kf = 0; kf < 4; ++kf) {
            uint32_t qf[4];
            const uint32_t qoff = (uint32_t)((mrow + a_r) * GSTR + kf * 16 + a_c8) * 2;
            ldsm_x4(qf, base + ATT_Q + qoff);
#pragma unroll
            for (int np = 0; np < 2; ++np) {             // nt2 pair {2np, 2np+1}
                uint32_t kf4[2][4];
#pragma unroll
                for (int j = 0; j < 2; ++j) {
                    const int nt2 = np * 2 + j;
                    const uint32_t koff =
                        (uint32_t)((nt2 * 16 + kb_r) * GSTR + kf * 16 + kb_c8) * 2;
                    ldsm_x4(kf4[j], kvb + koff);
                }
#pragma unroll
                for (int j = 0; j < 2; ++j)
#pragma unroll
                    for (int hh = 0; hh < 2; ++hh)
                        mma16816(sacc[np * 4 + j * 2 + hh], qf, kf4[j] + hh * 2);
            }
        }

        // ---- scale (log2 domain) + mask ----
#pragma unroll
        for (int nt = 0; nt < 8; ++nt) {
            const float ma = smask[nt * 8 + cbase]     ? 0.f : -1e30f;
            const float mb = smask[nt * 8 + cbase + 1] ? 0.f : -1e30f;
            sacc[nt][0] = sacc[nt][0] * SCALE_L2E + ma;
            sacc[nt][1] = sacc[nt][1] * SCALE_L2E + mb;
            sacc[nt][2] = sacc[nt][2] * SCALE_L2E + ma;
            sacc[nt][3] = sacc[nt][3] * SCALE_L2E + mb;
        }

        // ---- online softmax (rows r=lane>>2 and r+8), exp2 in-place ----
        float mx0 = -1e30f, mx1 = -1e30f;
#pragma unroll
        for (int nt = 0; nt < 8; ++nt) {
            mx0 = fmaxf(mx0, fmaxf(sacc[nt][0], sacc[nt][1]));
            mx1 = fmaxf(mx1, fmaxf(sacc[nt][2], sacc[nt][3]));
        }
        mx0 = fmaxf(mx0, __shfl_xor_sync(0xffffffffu, mx0, 1));
        mx0 = fmaxf(mx0, __shfl_xor_sync(0xffffffffu, mx0, 2));
        mx1 = fmaxf(mx1, __shfl_xor_sync(0xffffffffu, mx1, 1));
        mx1 = fmaxf(mx1, __shfl_xor_sync(0xffffffffu, mx1, 2));
        const float mn0 = fmaxf(m0s, mx0), mn1 = fmaxf(m1s, mx1);
        const float al0 = exp2f(m0s - mn0), al1 = exp2f(m1s - mn1);
        m0s = mn0; m1s = mn1;

        float rs0 = 0.f, rs1 = 0.f;
#pragma unroll
        for (int nt = 0; nt < 8; ++nt) {
            sacc[nt][0] = exp2f(sacc[nt][0] - mn0);
            sacc[nt][1] = exp2f(sacc[nt][1] - mn0);
            sacc[nt][2] = exp2f(sacc[nt][2] - mn1);
            sacc[nt][3] = exp2f(sacc[nt][3] - mn1);
            rs0 += sacc[nt][0] + sacc[nt][1];
            rs1 += sacc[nt][2] + sacc[nt][3];
        }
        rs0 += __shfl_xor_sync(0xffffffffu, rs0, 1);
        rs0 += __shfl_xor_sync(0xffffffffu, rs0, 2);
        rs1 += __shfl_xor_sync(0xffffffffu, rs1, 1);
        rs1 += __shfl_xor_sync(0xffffffffu, rs1, 2);
        l0s = l0s * al0 + rs0;
        l1s = l1s * al1 + rs1;
#pragma unroll
        for (int nt = 0; nt < 8; ++nt) {
            oacc[nt][0] *= al0; oacc[nt][1] *= al0;
            oacc[nt][2] *= al1; oacc[nt][3] *= al1;
        }

        // ---- O += P @ V (P single fp16) ----
#pragma unroll
        for (int kf2 = 0; kf2 < 4; ++kf2) {
            uint32_t pf[4];
            pf[0] = pack2h(sacc[2 * kf2][0],     sacc[2 * kf2][1]);
            pf[1] = pack2h(sacc[2 * kf2][2],     sacc[2 * kf2][3]);
            pf[2] = pack2h(sacc[2 * kf2 + 1][0], sacc[2 * kf2 + 1][1]);
            pf[3] = pack2h(sacc[2 * kf2 + 1][2], sacc[2 * kf2 + 1][3]);
#pragma unroll
            for (int dp = 0; dp < 2; ++dp) {             // dt2 pair {2dp, 2dp+1}
                uint32_t vf4[2][4];
#pragma unroll
                for (int j = 0; j < 2; ++j) {
                    const int dt2 = dp * 2 + j;
                    const uint32_t voff =
                        (uint32_t)((kf2 * 16 + vb_r) * GSTR + dt2 * 16 + vb_c8) * 2;
                    ldsm_x4t(vf4[j], kvb + 9216 + voff);
                }
#pragma unroll
                for (int j = 0; j < 2; ++j)
#pragma unroll
                    for (int hh = 0; hh < 2; ++hh)
                        mma16816(oacc[dp * 4 + j * 2 + hh], pf, vf4[j] + hh * 2);
            }
        }
        __syncthreads();   // done reading buf before refill
    }

    // epilogue: O /= l, store fp16 in (B,L,D)
    const float inv0 = 1.f / l0s, inv1 = 1.f / l1s;
    const int row0 = qb + mrow + (lane >> 2);
#pragma unroll
    for (int dt = 0; dt < 8; ++dt) {
        const int col = h * DK + dt * 8 + 2 * (lane & 3);
        const size_t i0 = ((size_t)b * SEQLEN + row0) * DMODEL + col;
        const size_t i1 = i0 + (size_t)8 * DMODEL;
        *(uint32_t*)(g_os + i0) = pack2h(oacc[dt][0] * inv0, oacc[dt][1] * inv0);
        *(uint32_t*)(g_os + i1) = pack2h(oacc[dt][2] * inv1, oacc[dt][3] * inv1);
    }
}

// ==================== launch ====================
extern "C" void kernel_launch(void* const* d_in, const int* in_sizes, int n_in,
                              void* d_out, int out_size)
{
    const float* x     = (const float*)d_in[0];
    const int*   amask = (const int*)  d_in[1];
    const float* w_qkv = (const float*)d_in[2];
    const float* b_qkv = (const float*)d_in[3];
    const float* w_out = (const float*)d_in[4];
    const float* b_out = (const float*)d_in[5];
    float*       out   = (float*)d_out;

    fp16 *x1, *wq, *wo, *os;
    cudaGetSymbolAddress((void**)&x1, g_x1);
    cudaGetSymbolAddress((void**)&wq, g_wq);
    cudaGetSymbolAddress((void**)&wo, g_wo);
    cudaGetSymbolAddress((void**)&os, g_os);

    // 0) prep: x -> fp16, W -> transposed fp16
    const int n4 = MTOT * DMODEL / 4;
    conv_x_kernel<<<(n4 + 255) / 256, 256>>>(x, x1, n4);
    ttrans_kernel<<<dim3(3 * DMODEL / 32, DMODEL / 32), 256>>>(w_qkv, wq, DMODEL, 3 * DMODEL);
    ttrans_kernel<<<dim3(DMODEL / 32, DMODEL / 32), 256>>>(w_out, wo, DMODEL, DMODEL);

    // 1) QKV projection (fp16, 128x64 tiles, occ 2)
    cudaFuncSetAttribute(gemm_mma<1>, cudaFuncAttributeMaxDynamicSharedMemorySize, G_SMEM);
    gemm_mma<1><<<dim3(3 * DMODEL / 64, MTOT / 128), 256, G_SMEM>>>(
        x1, wq, b_qkv, nullptr, 3 * DMODEL, DMODEL);

    // 2) flash attention (fp16, occ 2)
    cudaFuncSetAttribute(attn_mma, cudaFuncAttributeMaxDynamicSharedMemorySize, ATT_SMEM);
    attn_mma<<<dim3(SEQLEN / 128, BATCH * NHEADS), 256, ATT_SMEM>>>(amask);

    // 3) output projection (fp16)
    cudaFuncSetAttribute(gemm_mma<0>, cudaFuncAttributeMaxDynamicSharedMemorySize, G_SMEM);
    gemm_mma<0><<<dim3(DMODEL / 64, MTOT / 128), 256, G_SMEM>>>(
        os, wo, b_out, out, DMODEL, DMODEL);
}

// round 14
// speedup vs baseline: 3.6892x; 1.0589x over previous
#include <cuda_runtime.h>
#include <cuda_fp16.h>
#include <cstdint>

#define BATCH   2
#define NHEADS  12
#define SEQLEN  2048
#define DMODEL  768
#define DK      64
#define MTOT    (BATCH * SEQLEN)          // 4096

typedef __half fp16;

// ---------------- scratch (no allocations allowed) ----------------
__device__ __align__(256) fp16 g_x1[(size_t)MTOT * DMODEL];          // x fp16
__device__ __align__(256) fp16 g_wq[(size_t)3 * DMODEL * DMODEL];    // W_qkv^T [N][K]
__device__ __align__(256) fp16 g_wo[(size_t)DMODEL * DMODEL];        // W_out^T [N][K]
__device__ __align__(256) fp16 g_qs[(size_t)BATCH * NHEADS * SEQLEN * DK];
__device__ __align__(256) fp16 g_ks[(size_t)BATCH * NHEADS * SEQLEN * DK];
__device__ __align__(256) fp16 g_vs[(size_t)BATCH * NHEADS * SEQLEN * DK];
__device__ __align__(256) fp16 g_os[(size_t)MTOT * DMODEL];          // O fp16

// ==================== helpers ====================
__device__ __forceinline__ uint32_t smem_u32(const void* p) {
    uint32_t a;
    asm("{ .reg .u64 t; cvta.to.shared.u64 t, %1; cvt.u32.u64 %0, t; }" : "=r"(a) : "l"(p));
    return a;
}
__device__ __forceinline__ void mma16816(float* d, const uint32_t* a, const uint32_t* b) {
    asm volatile(
        "mma.sync.aligned.m16n8k16.row.col.f32.f16.f16.f32 "
        "{%0,%1,%2,%3}, {%4,%5,%6,%7}, {%8,%9}, {%0,%1,%2,%3};"
        : "+f"(d[0]), "+f"(d[1]), "+f"(d[2]), "+f"(d[3])
        : "r"(a[0]), "r"(a[1]), "r"(a[2]), "r"(a[3]), "r"(b[0]), "r"(b[1]));
}
__device__ __forceinline__ void ldsm_x4(uint32_t* r, uint32_t addr) {
    asm volatile("ldmatrix.sync.aligned.m8n8.x4.shared.b16 {%0,%1,%2,%3}, [%4];"
                 : "=r"(r[0]), "=r"(r[1]), "=r"(r[2]), "=r"(r[3]) : "r"(addr));
}
__device__ __forceinline__ void ldsm_x4t(uint32_t* r, uint32_t addr) {
    asm volatile("ldmatrix.sync.aligned.m8n8.x4.trans.shared.b16 {%0,%1,%2,%3}, [%4];"
                 : "=r"(r[0]), "=r"(r[1]), "=r"(r[2]), "=r"(r[3]) : "r"(addr));
}
__device__ __forceinline__ void cp_async16(uint32_t dst, const void* src) {
    asm volatile("cp.async.cg.shared.global [%0], [%1], 16;" :: "r"(dst), "l"(src));
}
__device__ __forceinline__ void cp_commit() {
    asm volatile("cp.async.commit_group;" ::: "memory");
}
template <int N>
__device__ __forceinline__ void cp_wait() {
    asm volatile("cp.async.wait_group %0;" :: "n"(N) : "memory");
}
__device__ __forceinline__ uint32_t pack2h(float x, float y) {
    __half2 hh = __floats2half2_rn(x, y);
    return *reinterpret_cast<uint32_t*>(&hh);
}

// ==================== prep kernels ====================
__global__ void conv_x_kernel(const float* __restrict__ x, fp16* __restrict__ o, int n4)
{
    int i = blockIdx.x * blockDim.x + threadIdx.x;
    if (i >= n4) return;
    float4 v = ((const float4*)x)[i];
    ((uint32_t*)o)[i * 2 + 0] = pack2h(v.x, v.y);
    ((uint32_t*)o)[i * 2 + 1] = pack2h(v.z, v.w);
}
// transpose W(K,N) -> [N][K] fp16
__global__ void ttrans_kernel(const float* __restrict__ W, fp16* __restrict__ T,
                              int K, int N)
{
    __shared__ float t[32][33];
    const int tx = threadIdx.x & 31, ty = threadIdx.x >> 5;   // 256 threads
    const int bn = blockIdx.x * 32, bk = blockIdx.y * 32;
#pragma unroll
    for (int j = 0; j < 4; ++j)
        t[ty + j * 8][tx] = W[(size_t)(bk + ty + j * 8) * N + bn + tx];
    __syncthreads();
#pragma unroll
    for (int j = 0; j < 4; ++j) {
        const int n = bn + ty + j * 8;
        const int k = bk + tx;
        T[(size_t)n * K + k] = __float2half_rn(t[tx][ty + j * 8]);
    }
}

// ==================== fp16 GEMM (128x128 tile, occ 2) ====================
// C(M,N) = A(M,K) @ B(N,K)^T + bias, fp32 accum; single fp16 operands.
// 8 warps (4m x 2n), warp tile 32x64, k-chunk 64, 2 cp.async stages.
#define GSTR 72
#define G_A   18432                       // 128 rows * 144 B
#define G_STAGE (2 * G_A)                 // 36864 (A + B, each 128 rows)
#define G_SMEM  (2 * G_STAGE)             // 73728

__device__ __forceinline__ void gemm_issue(
    uint32_t sb, int tid, const fp16* A1, const fp16* B1,
    int m0, int n0, int kc, int K)
{
#pragma unroll
    for (int i = 0; i < 8; ++i) {
        const int idx = i * 256 + tid;       // 0..2047
        const int arr = idx >> 10;           // 0 = A, 1 = B
        const int rem = idx & 1023;          // 128 rows x 8 segs
        const int row = rem >> 3, seg = rem & 7;
        const fp16* src = arr ? B1 : A1;
        const int grow = (arr ? n0 : m0) + row;
        cp_async16(sb + arr * G_A + (uint32_t)(row * GSTR + seg * 8) * 2,
                   src + (size_t)grow * K + kc + seg * 8);
    }
    cp_commit();
}

template <int MODE>
__global__ __launch_bounds__(256, 2)
void gemm_mma(const fp16* __restrict__ A1, const fp16* __restrict__ B1,
              const float* __restrict__ bias, float* __restrict__ out,
              int N, int K)
{
    extern __shared__ char smc[];
    const uint32_t base = smem_u32(smc);

    const int tid = threadIdx.x, lane = tid & 31, wid = tid >> 5;
    const int wm = wid & 3, wn = wid >> 2;        // 4m x 2n
    const int m0 = blockIdx.y * 128, n0 = blockIdx.x * 128;

    float acc[2][8][4];
#pragma unroll
    for (int t = 0; t < 2; ++t)
#pragma unroll
        for (int n = 0; n < 8; ++n)
#pragma unroll
            for (int j = 0; j < 4; ++j) acc[t][n][j] = 0.f;

    const int a_r  = lane & 15;
    const int a_c8 = (lane >> 4) * 8;
    const int b_r  = (lane & 7) + ((lane >> 4) << 3);
    const int b_c8 = ((lane >> 3) & 1) * 8;

    const int NC = K / 64;                  // 12
    gemm_issue(base, tid, A1, B1, m0, n0, 0, K);

    for (int c = 0; c < NC; ++c) {
        const int buf = c & 1;
        if (c + 1 < NC) {
            gemm_issue(base + (buf ^ 1) * G_STAGE, tid, A1, B1,
                       m0, n0, (c + 1) * 64, K);
            cp_wait<1>();
        } else {
            cp_wait<0>();
        }
        __syncthreads();

        const uint32_t sb = base + buf * G_STAGE;
#pragma unroll
        for (int kf = 0; kf < 4; ++kf) {
            uint32_t af[2][4];
#pragma unroll
            for (int t = 0; t < 2; ++t) {
                const uint32_t off =
                    (uint32_t)((wm * 32 + t * 16 + a_r) * GSTR + kf * 16 + a_c8) * 2;
                ldsm_x4(af[t], sb + off);
            }
#pragma unroll
            for (int nt2 = 0; nt2 < 4; ++nt2) {
                const uint32_t off = G_A +
                    (uint32_t)((wn * 64 + nt2 * 16 + b_r) * GSTR + kf * 16 + b_c8) * 2;
                uint32_t bf[4];
                ldsm_x4(bf, sb + off);
#pragma unroll
                for (int t = 0; t < 2; ++t)
#pragma unroll
                    for (int h = 0; h < 2; ++h)
                        mma16816(acc[t][nt2 * 2 + h], af[t], bf + h * 2);
            }
        }
        __syncthreads();
    }

    // epilogue
#pragma unroll
    for (int t = 0; t < 2; ++t) {
        const int gr0 = m0 + wm * 32 + t * 16 + (lane >> 2);
#pragma unroll
        for (int nt = 0; nt < 8; ++nt) {
            const int gn = n0 + wn * 64 + nt * 8 + 2 * (lane & 3);
            const float b0 = bias[gn], b1 = bias[gn + 1];
            const float v00 = acc[t][nt][0] + b0, v01 = acc[t][nt][1] + b1;
            const float v10 = acc[t][nt][2] + b0, v11 = acc[t][nt][3] + b1;
            if (MODE == 0) {
                *(float2*)&out[(size_t)gr0 * N + gn]       = make_float2(v00, v01);
                *(float2*)&out[(size_t)(gr0 + 8) * N + gn] = make_float2(v10, v11);
            } else {
                const int part = gn / DMODEL;
                const int w = gn % DMODEL;
                const int hh = w >> 6, dd = w & 63;
                const int bb = gr0 >> 11;
                const int ll0 = gr0 & 2047;
                const size_t i0 = (((size_t)bb * NHEADS + hh) * SEQLEN + ll0) * DK + dd;
                const size_t i1 = i0 + 8 * DK;
                fp16* dst = (part == 0) ? g_qs : (part == 1) ? g_ks : g_vs;
                *(uint32_t*)(dst + i0) = pack2h(v00, v01);
                *(uint32_t*)(dst + i1) = pack2h(v10, v11);
            }
        }
    }
}

// ==================== flash attention (fp16, occ 2) ====================
// BM=128, BN=64, 256 thr / 8 warps; Q/K/V/P all single fp16, fp32 accum.
#define KV_STG    18432                   // k 0 | v 9216
#define ATT_Q     0
#define ATT_KV    18432
#define ATT_MASK  (18432 + 2 * KV_STG)    // 55296
#define ATT_SMEM  (ATT_MASK + 512)        // 55808
#define SCALE_L2E 0.1803368867f           // 0.125 * log2(e)

__device__ __forceinline__ void attn_issue_kv(
    uint32_t base, int tid, const fp16* Ks, const fp16* Vs,
    const int* amask_row, int kb, int buf)
{
    const uint32_t sb = base + ATT_KV + buf * KV_STG;
#pragma unroll
    for (int i = 0; i < 4; ++i) {
        const int idx = i * 256 + tid;      // 2 arrays x 512
        const int arr = idx >> 9;
        const int rem = idx & 511;
        const int row = rem >> 3, seg = rem & 7;
        const fp16* src = arr ? Vs : Ks;
        cp_async16(sb + arr * 9216 + (uint32_t)(row * GSTR + seg * 8) * 2,
                   src + (size_t)(kb + row) * DK + seg * 8);
    }
    if (tid < 16)
        cp_async16(base + ATT_MASK + buf * 256 + tid * 16, amask_row + kb + tid * 4);
    cp_commit();
}

__global__ __launch_bounds__(256, 2)
void attn_mma(const int* __restrict__ amask)
{
    extern __shared__ char smc[];
    const uint32_t base = smem_u32(smc);

    const int tid = threadIdx.x, lane = tid & 31, wid = tid >> 5;
    const int bh = blockIdx.y, b = bh / NHEADS, h = bh % NHEADS;
    const int qb = blockIdx.x * 128;

    const fp16* Qs = g_qs + (size_t)bh * SEQLEN * DK;
    const fp16* Ks = g_ks + (size_t)bh * SEQLEN * DK;
    const fp16* Vs = g_vs + (size_t)bh * SEQLEN * DK;
    const int* amask_row = amask + (size_t)b * SEQLEN;

    // prologue G0: Q + KV chunk 0 + mask 0 (one commit)
#pragma unroll
    for (int i = 0; i < 4; ++i) {
        const int idx = i * 256 + tid;          // 0..1023
        const int row = idx >> 3, seg = idx & 7;
        cp_async16(base + ATT_Q + (uint32_t)(row * GSTR + seg * 8) * 2,
                   Qs + (size_t)(qb + row) * DK + seg * 8);
    }
    attn_issue_kv(base, tid, Ks, Vs, amask_row, 0, 0);

    float m0s = -1e30f, m1s = -1e30f, l0s = 0.f, l1s = 0.f;
    float oacc[8][4];
#pragma unroll
    for (int n = 0; n < 8; ++n)
#pragma unroll
        for (int j = 0; j < 4; ++j) oacc[n][j] = 0.f;

    const int a_r  = lane & 15;
    const int a_c8 = (lane >> 4) * 8;
    const int kb_r = (lane & 7) + ((lane >> 4) << 3);
    const int kb_c8 = ((lane >> 3) & 1) * 8;
    const int vb_r = (lane & 7) + ((lane >> 3) & 1) * 8;
    const int vb_c8 = (lane >> 4) * 8;
    const int mrow = wid * 16;
    const int cbase = 2 * (lane & 3);

    const int NIT = SEQLEN / 64;   // 32
    for (int it = 0; it < NIT; ++it) {
        const int buf = it & 1;
        if (it + 1 < NIT) {
            attn_issue_kv(base, tid, Ks, Vs, amask_row, (it + 1) * 64, buf ^ 1);
            cp_wait<1>();
        } else {
            cp_wait<0>();
        }
        __syncthreads();

        const uint32_t kvb = base + ATT_KV + buf * KV_STG;
        const int* smask = (const int*)(smc + ATT_MASK + buf * 256);

        // ---- S = Q @ K^T ----
        float sacc[8][4];
#pragma unroll
        for (int n = 0; n < 8; ++n)
#pragma unroll
            for (int j = 0; j < 4; ++j) sacc[n][j] = 0.f;

#pragma unroll
        for (int kf = 0; kf < 4; ++kf) {
            uint32_t qf[4];
            const uint32_t qoff = (uint32_t)((mrow + a_r) * GSTR + kf * 16 + a_c8) * 2;
            ldsm_x4(qf, base + ATT_Q + qoff);
#pragma unroll
            for (int np = 0; np < 2; ++np) {             // nt2 pair {2np, 2np+1}
                uint32_t kf4[2][4];
#pragma unroll
                for (int j = 0; j < 2; ++j) {
                    const int nt2 = np * 2 + j;
                    const uint32_t koff =
                        (uint32_t)((nt2 * 16 + kb_r) * GSTR + kf * 16 + kb_c8) * 2;
                    ldsm_x4(kf4[j], kvb + koff);
                }
#pragma unroll
                for (int j = 0; j < 2; ++j)
#pragma unroll
                    for (int hh = 0; hh < 2; ++hh)
                        mma16816(sacc[np * 4 + j * 2 + hh], qf, kf4[j] + hh * 2);
            }
        }

        // ---- scale (log2 domain) + mask ----
#pragma unroll
        for (int nt = 0; nt < 8; ++nt) {
            const float ma = smask[nt * 8 + cbase]     ? 0.f : -1e30f;
            const float mb = smask[nt * 8 + cbase + 1] ? 0.f : -1e30f;
            sacc[nt][0] = sacc[nt][0] * SCALE_L2E + ma;
            sacc[nt][1] = sacc[nt][1] * SCALE_L2E + mb;
            sacc[nt][2] = sacc[nt][2] * SCALE_L2E + ma;
            sacc[nt][3] = sacc[nt][3] * SCALE_L2E + mb;
        }

        // ---- online softmax (rows r=lane>>2 and r+8), exp2 in-place ----
        float mx0 = -1e30f, mx1 = -1e30f;
#pragma unroll
        for (int nt = 0; nt < 8; ++nt) {
            mx0 = fmaxf(mx0, fmaxf(sacc[nt][0], sacc[nt][1]));
            mx1 = fmaxf(mx1, fmaxf(sacc[nt][2], sacc[nt][3]));
        }
        mx0 = fmaxf(mx0, __shfl_xor_sync(0xffffffffu, mx0, 1));
        mx0 = fmaxf(mx0, __shfl_xor_sync(0xffffffffu, mx0, 2));
        mx1 = fmaxf(mx1, __shfl_xor_sync(0xffffffffu, mx1, 1));
        mx1 = fmaxf(mx1, __shfl_xor_sync(0xffffffffu, mx1, 2));
        const float mn0 = fmaxf(m0s, mx0), mn1 = fmaxf(m1s, mx1);
        const float al0 = exp2f(m0s - mn0), al1 = exp2f(m1s - mn1);
        m0s = mn0; m1s = mn1;

        float rs0 = 0.f, rs1 = 0.f;
#pragma unroll
        for (int nt = 0; nt < 8; ++nt) {
            sacc[nt][0] = exp2f(sacc[nt][0] - mn0);
            sacc[nt][1] = exp2f(sacc[nt][1] - mn0);
            sacc[nt][2] = exp2f(sacc[nt][2] - mn1);
            sacc[nt][3] = exp2f(sacc[nt][3] - mn1);
            rs0 += sacc[nt][0] + sacc[nt][1];
            rs1 += sacc[nt][2] + sacc[nt][3];
        }
        rs0 += __shfl_xor_sync(0xffffffffu, rs0, 1);
        rs0 += __shfl_xor_sync(0xffffffffu, rs0, 2);
        rs1 += __shfl_xor_sync(0xffffffffu, rs1, 1);
        rs1 += __shfl_xor_sync(0xffffffffu, rs1, 2);
        l0s = l0s * al0 + rs0;
        l1s = l1s * al1 + rs1;
#pragma unroll
        for (int nt = 0; nt < 8; ++nt) {
            oacc[nt][0] *= al0; oacc[nt][1] *= al0;
            oacc[nt][2] *= al1; oacc[nt][3] *= al1;
        }

        // ---- O += P @ V (P single fp16) ----
#pragma unroll
        for (int kf2 = 0; kf2 < 4; ++kf2) {
            uint32_t pf[4];
            pf[0] = pack2h(sacc[2 * kf2][0],     sacc[2 * kf2][1]);
            pf[1] = pack2h(sacc[2 * kf2][2],     sacc[2 * kf2][3]);
            pf[2] = pack2h(sacc[2 * kf2 + 1][0], sacc[2 * kf2 + 1][1]);
            pf[3] = pack2h(sacc[2 * kf2 + 1][2], sacc[2 * kf2 + 1][3]);
#pragma unroll
            for (int dp = 0; dp < 2; ++dp) {             // dt2 pair {2dp, 2dp+1}
                uint32_t vf4[2][4];
#pragma unroll
                for (int j = 0; j < 2; ++j) {
                    const int dt2 = dp * 2 + j;
                    const uint32_t voff =
                        (uint32_t)((kf2 * 16 + vb_r) * GSTR + dt2 * 16 + vb_c8) * 2;
                    ldsm_x4t(vf4[j], kvb + 9216 + voff);
                }
#pragma unroll
                for (int j = 0; j < 2; ++j)
#pragma unroll
                    for (int hh = 0; hh < 2; ++hh)
                        mma16816(oacc[dp * 4 + j * 2 + hh], pf, vf4[j] + hh * 2);
            }
        }
        __syncthreads();   // done reading buf before refill
    }

    // epilogue: O /= l, store fp16 in (B,L,D)
    const float inv0 = 1.f / l0s, inv1 = 1.f / l1s;
    const int row0 = qb + mrow + (lane >> 2);
#pragma unroll
    for (int dt = 0; dt < 8; ++dt) {
        const int col = h * DK + dt * 8 + 2 * (lane & 3);
        const size_t i0 = ((size_t)b * SEQLEN + row0) * DMODEL + col;
        const size_t i1 = i0 + (size_t)8 * DMODEL;
        *(uint32_t*)(g_os + i0) = pack2h(oacc[dt][0] * inv0, oacc[dt][1] * inv0);
        *(uint32_t*)(g_os + i1) = pack2h(oacc[dt][2] * inv1, oacc[dt][3] * inv1);
    }
}

// ==================== launch ====================
extern "C" void kernel_launch(void* const* d_in, const int* in_sizes, int n_in,
                              void* d_out, int out_size)
{
    const float* x     = (const float*)d_in[0];
    const int*   amask = (const int*)  d_in[1];
    const float* w_qkv = (const float*)d_in[2];
    const float* b_qkv = (const float*)d_in[3];
    const float* w_out = (const float*)d_in[4];
    const float* b_out = (const float*)d_in[5];
    float*       out   = (float*)d_out;

    fp16 *x1, *wq, *wo, *os;
    cudaGetSymbolAddress((void**)&x1, g_x1);
    cudaGetSymbolAddress((void**)&wq, g_wq);
    cudaGetSymbolAddress((void**)&wo, g_wo);
    cudaGetSymbolAddress((void**)&os, g_os);

    // 0) prep: x -> fp16, W -> transposed fp16
    const int n4 = MTOT * DMODEL / 4;
    conv_x_kernel<<<(n4 + 255) / 256, 256>>>(x, x1, n4);
    ttrans_kernel<<<dim3(3 * DMODEL / 32, DMODEL / 32), 256>>>(w_qkv, wq, DMODEL, 3 * DMODEL);
    ttrans_kernel<<<dim3(DMODEL / 32, DMODEL / 32), 256>>>(w_out, wo, DMODEL, DMODEL);

    // 1) QKV projection (fp16, 128x128 tiles, occ 2)
    cudaFuncSetAttribute(gemm_mma<1>, cudaFuncAttributeMaxDynamicSharedMemorySize, G_SMEM);
    gemm_mma<1><<<dim3(3 * DMODEL / 128, MTOT / 128), 256, G_SMEM>>>(
        x1, wq, b_qkv, nullptr, 3 * DMODEL, DMODEL);

    // 2) flash attention (fp16, occ 2)
    cudaFuncSetAttribute(attn_mma, cudaFuncAttributeMaxDynamicSharedMemorySize, ATT_SMEM);
    attn_mma<<<dim3(SEQLEN / 128, BATCH * NHEADS), 256, ATT_SMEM>>>(amask);

    // 3) output projection (fp16, 128x128 tiles)
    cudaFuncSetAttribute(gemm_mma<0>, cudaFuncAttributeMaxDynamicSharedMemorySize, G_SMEM);
    gemm_mma<0><<<dim3(DMODEL / 128, MTOT / 128), 256, G_SMEM>>>(
        os, wo, b_out, out, DMODEL, DMODEL);
}

// round 15
// speedup vs baseline: 3.6898x; 1.0002x over previous
#include <cuda_runtime.h>
#include <cuda_fp16.h>
#include <cstdint>

#define BATCH   2
#define NHEADS  12
#define SEQLEN  2048
#define DMODEL  768
#define DK      64
#define MTOT    (BATCH * SEQLEN)          // 4096

typedef __half fp16;

// ---------------- scratch (no allocations allowed) ----------------
__device__ __align__(256) fp16 g_x1[(size_t)MTOT * DMODEL];          // x fp16
__device__ __align__(256) fp16 g_wq[(size_t)3 * DMODEL * DMODEL];    // W_qkv^T [N][K]
__device__ __align__(256) fp16 g_wo[(size_t)DMODEL * DMODEL];        // W_out^T [N][K]
__device__ __align__(256) fp16 g_qs[(size_t)BATCH * NHEADS * SEQLEN * DK];
__device__ __align__(256) fp16 g_ks[(size_t)BATCH * NHEADS * SEQLEN * DK];
__device__ __align__(256) fp16 g_vs[(size_t)BATCH * NHEADS * SEQLEN * DK];
__device__ __align__(256) fp16 g_os[(size_t)MTOT * DMODEL];          // O fp16

// ==================== helpers ====================
__device__ __forceinline__ uint32_t smem_u32(const void* p) {
    uint32_t a;
    asm("{ .reg .u64 t; cvta.to.shared.u64 t, %1; cvt.u32.u64 %0, t; }" : "=r"(a) : "l"(p));
    return a;
}
__device__ __forceinline__ void mma16816(float* d, const uint32_t* a, const uint32_t* b) {
    asm volatile(
        "mma.sync.aligned.m16n8k16.row.col.f32.f16.f16.f32 "
        "{%0,%1,%2,%3}, {%4,%5,%6,%7}, {%8,%9}, {%0,%1,%2,%3};"
        : "+f"(d[0]), "+f"(d[1]), "+f"(d[2]), "+f"(d[3])
        : "r"(a[0]), "r"(a[1]), "r"(a[2]), "r"(a[3]), "r"(b[0]), "r"(b[1]));
}
__device__ __forceinline__ void ldsm_x4(uint32_t* r, uint32_t addr) {
    asm volatile("ldmatrix.sync.aligned.m8n8.x4.shared.b16 {%0,%1,%2,%3}, [%4];"
                 : "=r"(r[0]), "=r"(r[1]), "=r"(r[2]), "=r"(r[3]) : "r"(addr));
}
__device__ __forceinline__ void ldsm_x4t(uint32_t* r, uint32_t addr) {
    asm volatile("ldmatrix.sync.aligned.m8n8.x4.trans.shared.b16 {%0,%1,%2,%3}, [%4];"
                 : "=r"(r[0]), "=r"(r[1]), "=r"(r[2]), "=r"(r[3]) : "r"(addr));
}
__device__ __forceinline__ void cp_async16(uint32_t dst, const void* src) {
    asm volatile("cp.async.cg.shared.global [%0], [%1], 16;" :: "r"(dst), "l"(src));
}
__device__ __forceinline__ void cp_commit() {
    asm volatile("cp.async.commit_group;" ::: "memory");
}
template <int N>
__device__ __forceinline__ void cp_wait() {
    asm volatile("cp.async.wait_group %0;" :: "n"(N) : "memory");
}
__device__ __forceinline__ uint32_t pack2h(float x, float y) {
    __half2 hh = __floats2half2_rn(x, y);
    return *reinterpret_cast<uint32_t*>(&hh);
}
// packed exp2: P = 2^(x,y) as fp16x2 (ex2.approx.f16x2 via h2exp2)
__device__ __forceinline__ uint32_t exp2_pack(float x, float y) {
    __half2 a = __floats2half2_rn(x, y);
    __half2 p = h2exp2(a);
    return *reinterpret_cast<uint32_t*>(&p);
}
__device__ __forceinline__ float2 unpack2h(uint32_t u) {
    __half2 hh = *reinterpret_cast<__half2*>(&u);
    return __half22float2(hh);
}

// ==================== prep kernels ====================
__global__ void conv_x_kernel(const float* __restrict__ x, fp16* __restrict__ o, int n4)
{
    int i = blockIdx.x * blockDim.x + threadIdx.x;
    if (i >= n4) return;
    float4 v = ((const float4*)x)[i];
    ((uint32_t*)o)[i * 2 + 0] = pack2h(v.x, v.y);
    ((uint32_t*)o)[i * 2 + 1] = pack2h(v.z, v.w);
}
// transpose W(K,N) -> [N][K] fp16
__global__ void ttrans_kernel(const float* __restrict__ W, fp16* __restrict__ T,
                              int K, int N)
{
    __shared__ float t[32][33];
    const int tx = threadIdx.x & 31, ty = threadIdx.x >> 5;   // 256 threads
    const int bn = blockIdx.x * 32, bk = blockIdx.y * 32;
#pragma unroll
    for (int j = 0; j < 4; ++j)
        t[ty + j * 8][tx] = W[(size_t)(bk + ty + j * 8) * N + bn + tx];
    __syncthreads();
#pragma unroll
    for (int j = 0; j < 4; ++j) {
        const int n = bn + ty + j * 8;
        const int k = bk + tx;
        T[(size_t)n * K + k] = __float2half_rn(t[tx][ty + j * 8]);
    }
}

// ==================== fp16 GEMM (128x128 tile, occ 2) ====================
#define GSTR 72
#define G_A   18432                       // 128 rows * 144 B
#define G_STAGE (2 * G_A)                 // 36864
#define G_SMEM  (2 * G_STAGE)             // 73728

__device__ __forceinline__ void gemm_issue(
    uint32_t sb, int tid, const fp16* A1, const fp16* B1,
    int m0, int n0, int kc, int K)
{
#pragma unroll
    for (int i = 0; i < 8; ++i) {
        const int idx = i * 256 + tid;       // 0..2047
        const int arr = idx >> 10;           // 0 = A, 1 = B
        const int rem = idx & 1023;          // 128 rows x 8 segs
        const int row = rem >> 3, seg = rem & 7;
        const fp16* src = arr ? B1 : A1;
        const int grow = (arr ? n0 : m0) + row;
        cp_async16(sb + arr * G_A + (uint32_t)(row * GSTR + seg * 8) * 2,
                   src + (size_t)grow * K + kc + seg * 8);
    }
    cp_commit();
}

template <int MODE>
__global__ __launch_bounds__(256, 2)
void gemm_mma(const fp16* __restrict__ A1, const fp16* __restrict__ B1,
              const float* __restrict__ bias, float* __restrict__ out,
              int N, int K)
{
    extern __shared__ char smc[];
    const uint32_t base = smem_u32(smc);

    const int tid = threadIdx.x, lane = tid & 31, wid = tid >> 5;
    const int wm = wid & 3, wn = wid >> 2;        // 4m x 2n
    const int m0 = blockIdx.y * 128, n0 = blockIdx.x * 128;

    float acc[2][8][4];
#pragma unroll
    for (int t = 0; t < 2; ++t)
#pragma unroll
        for (int n = 0; n < 8; ++n)
#pragma unroll
            for (int j = 0; j < 4; ++j) acc[t][n][j] = 0.f;

    const int a_r  = lane & 15;
    const int a_c8 = (lane >> 4) * 8;
    const int b_r  = (lane & 7) + ((lane >> 4) << 3);
    const int b_c8 = ((lane >> 3) & 1) * 8;

    const int NC = K / 64;                  // 12
    gemm_issue(base, tid, A1, B1, m0, n0, 0, K);

    for (int c = 0; c < NC; ++c) {
        const int buf = c & 1;
        if (c + 1 < NC) {
            gemm_issue(base + (buf ^ 1) * G_STAGE, tid, A1, B1,
                       m0, n0, (c + 1) * 64, K);
            cp_wait<1>();
        } else {
            cp_wait<0>();
        }
        __syncthreads();

        const uint32_t sb = base + buf * G_STAGE;
#pragma unroll
        for (int kf = 0; kf < 4; ++kf) {
            uint32_t af[2][4];
#pragma unroll
            for (int t = 0; t < 2; ++t) {
                const uint32_t off =
                    (uint32_t)((wm * 32 + t * 16 + a_r) * GSTR + kf * 16 + a_c8) * 2;
                ldsm_x4(af[t], sb + off);
            }
#pragma unroll
            for (int nt2 = 0; nt2 < 4; ++nt2) {
                const uint32_t off = G_A +
                    (uint32_t)((wn * 64 + nt2 * 16 + b_r) * GSTR + kf * 16 + b_c8) * 2;
                uint32_t bf[4];
                ldsm_x4(bf, sb + off);
#pragma unroll
                for (int t = 0; t < 2; ++t)
#pragma unroll
                    for (int h = 0; h < 2; ++h)
                        mma16816(acc[t][nt2 * 2 + h], af[t], bf + h * 2);
            }
        }
        __syncthreads();
    }

    // epilogue
#pragma unroll
    for (int t = 0; t < 2; ++t) {
        const int gr0 = m0 + wm * 32 + t * 16 + (lane >> 2);
#pragma unroll
        for (int nt = 0; nt < 8; ++nt) {
            const int gn = n0 + wn * 64 + nt * 8 + 2 * (lane & 3);
            const float b0 = bias[gn], b1 = bias[gn + 1];
            const float v00 = acc[t][nt][0] + b0, v01 = acc[t][nt][1] + b1;
            const float v10 = acc[t][nt][2] + b0, v11 = acc[t][nt][3] + b1;
            if (MODE == 0) {
                *(float2*)&out[(size_t)gr0 * N + gn]       = make_float2(v00, v01);
                *(float2*)&out[(size_t)(gr0 + 8) * N + gn] = make_float2(v10, v11);
            } else {
                const int part = gn / DMODEL;
                const int w = gn % DMODEL;
                const int hh = w >> 6, dd = w & 63;
                const int bb = gr0 >> 11;
                const int ll0 = gr0 & 2047;
                const size_t i0 = (((size_t)bb * NHEADS + hh) * SEQLEN + ll0) * DK + dd;
                const size_t i1 = i0 + 8 * DK;
                fp16* dst = (part == 0) ? g_qs : (part == 1) ? g_ks : g_vs;
                *(uint32_t*)(dst + i0) = pack2h(v00, v01);
                *(uint32_t*)(dst + i1) = pack2h(v10, v11);
            }
        }
    }
}

// ==================== flash attention (fp16, occ 2, f16x2 exp) ==========
// BM=128, KV chunk 128 processed as two 64-col halves; 2 KV stages.
#define KV_STG    36864                   // k(128x144) 0 | v 18432
#define ATT_Q     0
#define ATT_KV    18432
#define ATT_MASK  (18432 + 2 * KV_STG)    // 92160
#define ATT_SMEM  (ATT_MASK + 1024)       // 93184
#define SCALE_L2E 0.1803368867f           // 0.125 * log2(e)

__device__ __forceinline__ void attn_issue_kv(
    uint32_t base, int tid, const fp16* Ks, const fp16* Vs,
    const int* amask_row, int kb, int buf)
{
    const uint32_t sb = base + ATT_KV + buf * KV_STG;
#pragma unroll
    for (int i = 0; i < 8; ++i) {
        const int idx = i * 256 + tid;      // 2 arrays x 1024
        const int arr = idx >> 10;
        const int rem = idx & 1023;         // 128 rows x 8 segs
        const int row = rem >> 3, seg = rem & 7;
        const fp16* src = arr ? Vs : Ks;
        cp_async16(sb + arr * 18432 + (uint32_t)(row * GSTR + seg * 8) * 2,
                   src + (size_t)(kb + row) * DK + seg * 8);
    }
    if (tid < 32)
        cp_async16(base + ATT_MASK + buf * 512 + tid * 16, amask_row + kb + tid * 4);
    cp_commit();
}

__global__ __launch_bounds__(256, 2)
void attn_mma(const int* __restrict__ amask)
{
    extern __shared__ char smc[];
    const uint32_t base = smem_u32(smc);

    const int tid = threadIdx.x, lane = tid & 31, wid = tid >> 5;
    const int bh = blockIdx.y, b = bh / NHEADS, h = bh % NHEADS;
    const int qb = blockIdx.x * 128;

    const fp16* Qs = g_qs + (size_t)bh * SEQLEN * DK;
    const fp16* Ks = g_ks + (size_t)bh * SEQLEN * DK;
    const fp16* Vs = g_vs + (size_t)bh * SEQLEN * DK;
    const int* amask_row = amask + (size_t)b * SEQLEN;

    // prologue G0: Q + KV chunk 0 + mask 0 (one commit)
#pragma unroll
    for (int i = 0; i < 4; ++i) {
        const int idx = i * 256 + tid;          // 0..1023
        const int row = idx >> 3, seg = idx & 7;
        cp_async16(base + ATT_Q + (uint32_t)(row * GSTR + seg * 8) * 2,
                   Qs + (size_t)(qb + row) * DK + seg * 8);
    }
    attn_issue_kv(base, tid, Ks, Vs, amask_row, 0, 0);

    float m0s = -1e30f, m1s = -1e30f, l0s = 0.f, l1s = 0.f;
    float oacc[8][4];
#pragma unroll
    for (int n = 0; n < 8; ++n)
#pragma unroll
        for (int j = 0; j < 4; ++j) oacc[n][j] = 0.f;

    const int a_r  = lane & 15;
    const int a_c8 = (lane >> 4) * 8;
    const int kb_r = (lane & 7) + ((lane >> 4) << 3);
    const int kb_c8 = ((lane >> 3) & 1) * 8;
    const int vb_r = (lane & 7) + ((lane >> 3) & 1) * 8;
    const int vb_c8 = (lane >> 4) * 8;
    const int mrow = wid * 16;
    const int cbase = 2 * (lane & 3);

    const int NIT = SEQLEN / 128;   // 16 outer iterations
    for (int it = 0; it < NIT; ++it) {
        const int buf = it & 1;
        if (it + 1 < NIT) {
            attn_issue_kv(base, tid, Ks, Vs, amask_row, (it + 1) * 128, buf ^ 1);
            cp_wait<1>();
        } else {
            cp_wait<0>();
        }
        __syncthreads();

        const uint32_t kvb = base + ATT_KV + buf * KV_STG;
        const int* smask = (const int*)(smc + ATT_MASK + buf * 512);

#pragma unroll
        for (int half = 0; half < 2; ++half) {
            const uint32_t kbase = kvb + (uint32_t)(half * 64) * GSTR * 2;
            const uint32_t vbase = kvb + 18432 + (uint32_t)(half * 64) * GSTR * 2;
            const int* smask_h = smask + half * 64;

            // ---- S = Q @ K^T (64 cols) ----
            float sacc[8][4];
#pragma unroll
            for (int n = 0; n < 8; ++n)
#pragma unroll
                for (int j = 0; j < 4; ++j) sacc[n][j] = 0.f;

#pragma unroll
            for (int kf = 0; kf < 4; ++kf) {
                uint32_t qf[4];
                const uint32_t qoff =
                    (uint32_t)((mrow + a_r) * GSTR + kf * 16 + a_c8) * 2;
                ldsm_x4(qf, base + ATT_Q + qoff);
#pragma unroll
                for (int np = 0; np < 2; ++np) {
                    uint32_t kf4[2][4];
#pragma unroll
                    for (int j = 0; j < 2; ++j) {
                        const int nt2 = np * 2 + j;
                        const uint32_t koff =
                            (uint32_t)((nt2 * 16 + kb_r) * GSTR + kf * 16 + kb_c8) * 2;
                        ldsm_x4(kf4[j], kbase + koff);
                    }
#pragma unroll
                    for (int j = 0; j < 2; ++j)
#pragma unroll
                        for (int hh = 0; hh < 2; ++hh)
                            mma16816(sacc[np * 4 + j * 2 + hh], qf, kf4[j] + hh * 2);
                }
            }

            // ---- scale (log2 domain) + mask ----
#pragma unroll
            for (int nt = 0; nt < 8; ++nt) {
                const float ma = smask_h[nt * 8 + cbase]     ? 0.f : -1e30f;
                const float mb = smask_h[nt * 8 + cbase + 1] ? 0.f : -1e30f;
                sacc[nt][0] = sacc[nt][0] * SCALE_L2E + ma;
                sacc[nt][1] = sacc[nt][1] * SCALE_L2E + mb;
                sacc[nt][2] = sacc[nt][2] * SCALE_L2E + ma;
                sacc[nt][3] = sacc[nt][3] * SCALE_L2E + mb;
            }

            // ---- online softmax: packed f16x2 exp2 ----
            float mx0 = -1e30f, mx1 = -1e30f;
#pragma unroll
            for (int nt = 0; nt < 8; ++nt) {
                mx0 = fmaxf(mx0, fmaxf(sacc[nt][0], sacc[nt][1]));
                mx1 = fmaxf(mx1, fmaxf(sacc[nt][2], sacc[nt][3]));
            }
            mx0 = fmaxf(mx0, __shfl_xor_sync(0xffffffffu, mx0, 1));
            mx0 = fmaxf(mx0, __shfl_xor_sync(0xffffffffu, mx0, 2));
            mx1 = fmaxf(mx1, __shfl_xor_sync(0xffffffffu, mx1, 1));
            mx1 = fmaxf(mx1, __shfl_xor_sync(0xffffffffu, mx1, 2));
            const float mn0 = fmaxf(m0s, mx0), mn1 = fmaxf(m1s, mx1);
            const float al0 = exp2f(m0s - mn0), al1 = exp2f(m1s - mn1);
            m0s = mn0; m1s = mn1;

            uint32_t ph2[8][2];          // P packed fp16 pairs (A-fragment layout)
            float rs0 = 0.f, rs1 = 0.f;
#pragma unroll
            for (int nt = 0; nt < 8; ++nt) {
                ph2[nt][0] = exp2_pack(sacc[nt][0] - mn0, sacc[nt][1] - mn0);
                ph2[nt][1] = exp2_pack(sacc[nt][2] - mn1, sacc[nt][3] - mn1);
                const float2 f0 = unpack2h(ph2[nt][0]);
                const float2 f1 = unpack2h(ph2[nt][1]);
                rs0 += f0.x + f0.y;
                rs1 += f1.x + f1.y;
            }
            rs0 += __shfl_xor_sync(0xffffffffu, rs0, 1);
            rs0 += __shfl_xor_sync(0xffffffffu, rs0, 2);
            rs1 += __shfl_xor_sync(0xffffffffu, rs1, 1);
            rs1 += __shfl_xor_sync(0xffffffffu, rs1, 2);
            l0s = l0s * al0 + rs0;
            l1s = l1s * al1 + rs1;
#pragma unroll
            for (int nt = 0; nt < 8; ++nt) {
                oacc[nt][0] *= al0; oacc[nt][1] *= al0;
                oacc[nt][2] *= al1; oacc[nt][3] *= al1;
            }

            // ---- O += P @ V ----
#pragma unroll
            for (int kf2 = 0; kf2 < 4; ++kf2) {
                uint32_t pf[4];
                pf[0] = ph2[2 * kf2][0];
                pf[1] = ph2[2 * kf2][1];
                pf[2] = ph2[2 * kf2 + 1][0];
                pf[3] = ph2[2 * kf2 + 1][1];
#pragma unroll
                for (int dp = 0; dp < 2; ++dp) {
                    uint32_t vf4[2][4];
#pragma unroll
                    for (int j = 0; j < 2; ++j) {
                        const int dt2 = dp * 2 + j;
                        const uint32_t voff =
                            (uint32_t)((kf2 * 16 + vb_r) * GSTR + dt2 * 16 + vb_c8) * 2;
                        ldsm_x4t(vf4[j], vbase + voff);
                    }
#pragma unroll
                    for (int j = 0; j < 2; ++j)
#pragma unroll
                        for (int hh = 0; hh < 2; ++hh)
                            mma16816(oacc[dp * 4 + j * 2 + hh], pf, vf4[j] + hh * 2);
                }
            }
        }
        __syncthreads();   // done reading buf before refill
    }

    // epilogue: O /= l, store fp16 in (B,L,D)
    const float inv0 = 1.f / l0s, inv1 = 1.f / l1s;
    const int row0 = qb + mrow + (lane >> 2);
#pragma unroll
    for (int dt = 0; dt < 8; ++dt) {
        const int col = h * DK + dt * 8 + 2 * (lane & 3);
        const size_t i0 = ((size_t)b * SEQLEN + row0) * DMODEL + col;
        const size_t i1 = i0 + (size_t)8 * DMODEL;
        *(uint32_t*)(g_os + i0) = pack2h(oacc[dt][0] * inv0, oacc[dt][1] * inv0);
        *(uint32_t*)(g_os + i1) = pack2h(oacc[dt][2] * inv1, oacc[dt][3] * inv1);
    }
}

// ==================== launch ====================
extern "C" void kernel_launch(void* const* d_in, const int* in_sizes, int n_in,
                              void* d_out, int out_size)
{
    const float* x     = (const float*)d_in[0];
    const int*   amask = (const int*)  d_in[1];
    const float* w_qkv = (const float*)d_in[2];
    const float* b_qkv = (const float*)d_in[3];
    const float* w_out = (const float*)d_in[4];
    const float* b_out = (const float*)d_in[5];
    float*       out   = (float*)d_out;

    fp16 *x1, *wq, *wo, *os;
    cudaGetSymbolAddress((void**)&x1, g_x1);
    cudaGetSymbolAddress((void**)&wq, g_wq);
    cudaGetSymbolAddress((void**)&wo, g_wo);
    cudaGetSymbolAddress((void**)&os, g_os);

    // 0) prep: x -> fp16, W -> transposed fp16
    const int n4 = MTOT * DMODEL / 4;
    conv_x_kernel<<<(n4 + 255) / 256, 256>>>(x, x1, n4);
    ttrans_kernel<<<dim3(3 * DMODEL / 32, DMODEL / 32), 256>>>(w_qkv, wq, DMODEL, 3 * DMODEL);
    ttrans_kernel<<<dim3(DMODEL / 32, DMODEL / 32), 256>>>(w_out, wo, DMODEL, DMODEL);

    // 1) QKV projection (fp16, 128x128 tiles, occ 2)
    cudaFuncSetAttribute(gemm_mma<1>, cudaFuncAttributeMaxDynamicSharedMemorySize, G_SMEM);
    gemm_mma<1><<<dim3(3 * DMODEL / 128, MTOT / 128), 256, G_SMEM>>>(
        x1, wq, b_qkv, nullptr, 3 * DMODEL, DMODEL);

    // 2) flash attention (fp16, occ 2, f16x2 exp)
    cudaFuncSetAttribute(attn_mma, cudaFuncAttributeMaxDynamicSharedMemorySize, ATT_SMEM);
    attn_mma<<<dim3(SEQLEN / 128, BATCH * NHEADS), 256, ATT_SMEM>>>(amask);

    // 3) output projection (fp16, 128x128 tiles)
    cudaFuncSetAttribute(gemm_mma<0>, cudaFuncAttributeMaxDynamicSharedMemorySize, G_SMEM);
    gemm_mma<0><<<dim3(DMODEL / 128, MTOT / 128), 256, G_SMEM>>>(
        os, wo, b_out, out, DMODEL, DMODEL);
}

// round 16
// speedup vs baseline: 3.7425x; 1.0143x over previous
#include <cuda_runtime.h>
#include <cuda_fp16.h>
#include <cstdint>

#define BATCH   2
#define NHEADS  12
#define SEQLEN  2048
#define DMODEL  768
#define DK      64
#define MTOT    (BATCH * SEQLEN)          // 4096

typedef __half fp16;

// ---------------- scratch (no allocations allowed) ----------------
__device__ __align__(256) fp16 g_x1[(size_t)MTOT * DMODEL];          // x fp16
__device__ __align__(256) fp16 g_wq[(size_t)3 * DMODEL * DMODEL];    // W_qkv^T [N][K]
__device__ __align__(256) fp16 g_wo[(size_t)DMODEL * DMODEL];        // W_out^T [N][K]
__device__ __align__(256) fp16 g_qs[(size_t)BATCH * NHEADS * SEQLEN * DK];
__device__ __align__(256) fp16 g_ks[(size_t)BATCH * NHEADS * SEQLEN * DK];
__device__ __align__(256) fp16 g_vs[(size_t)BATCH * NHEADS * SEQLEN * DK];
__device__ __align__(256) fp16 g_os[(size_t)MTOT * DMODEL];          // O fp16

// ==================== helpers ====================
__device__ __forceinline__ uint32_t smem_u32(const void* p) {
    uint32_t a;
    asm("{ .reg .u64 t; cvta.to.shared.u64 t, %1; cvt.u32.u64 %0, t; }" : "=r"(a) : "l"(p));
    return a;
}
__device__ __forceinline__ void mma16816(float* d, const uint32_t* a, const uint32_t* b) {
    asm volatile(
        "mma.sync.aligned.m16n8k16.row.col.f32.f16.f16.f32 "
        "{%0,%1,%2,%3}, {%4,%5,%6,%7}, {%8,%9}, {%0,%1,%2,%3};"
        : "+f"(d[0]), "+f"(d[1]), "+f"(d[2]), "+f"(d[3])
        : "r"(a[0]), "r"(a[1]), "r"(a[2]), "r"(a[3]), "r"(b[0]), "r"(b[1]));
}
__device__ __forceinline__ void ldsm_x4(uint32_t* r, uint32_t addr) {
    asm volatile("ldmatrix.sync.aligned.m8n8.x4.shared.b16 {%0,%1,%2,%3}, [%4];"
                 : "=r"(r[0]), "=r"(r[1]), "=r"(r[2]), "=r"(r[3]) : "r"(addr));
}
__device__ __forceinline__ void ldsm_x4t(uint32_t* r, uint32_t addr) {
    asm volatile("ldmatrix.sync.aligned.m8n8.x4.trans.shared.b16 {%0,%1,%2,%3}, [%4];"
                 : "=r"(r[0]), "=r"(r[1]), "=r"(r[2]), "=r"(r[3]) : "r"(addr));
}
__device__ __forceinline__ void cp_async16(uint32_t dst, const void* src) {
    asm volatile("cp.async.cg.shared.global [%0], [%1], 16;" :: "r"(dst), "l"(src));
}
__device__ __forceinline__ void cp_commit() {
    asm volatile("cp.async.commit_group;" ::: "memory");
}
template <int N>
__device__ __forceinline__ void cp_wait() {
    asm volatile("cp.async.wait_group %0;" :: "n"(N) : "memory");
}
__device__ __forceinline__ uint32_t pack2h(float x, float y) {
    __half2 hh = __floats2half2_rn(x, y);
    return *reinterpret_cast<uint32_t*>(&hh);
}

// ==================== prep kernels ====================
__global__ void conv_x_kernel(const float* __restrict__ x, fp16* __restrict__ o, int n4)
{
    int i = blockIdx.x * blockDim.x + threadIdx.x;
    if (i >= n4) return;
    float4 v = ((const float4*)x)[i];
    ((uint32_t*)o)[i * 2 + 0] = pack2h(v.x, v.y);
    ((uint32_t*)o)[i * 2 + 1] = pack2h(v.z, v.w);
}
// transpose W(K,N) -> [N][K] fp16
__global__ void ttrans_kernel(const float* __restrict__ W, fp16* __restrict__ T,
                              int K, int N)
{
    __shared__ float t[32][33];
    const int tx = threadIdx.x & 31, ty = threadIdx.x >> 5;   // 256 threads
    const int bn = blockIdx.x * 32, bk = blockIdx.y * 32;
#pragma unroll
    for (int j = 0; j < 4; ++j)
        t[ty + j * 8][tx] = W[(size_t)(bk + ty + j * 8) * N + bn + tx];
    __syncthreads();
#pragma unroll
    for (int j = 0; j < 4; ++j) {
        const int n = bn + ty + j * 8;
        const int k = bk + tx;
        T[(size_t)n * K + k] = __float2half_rn(t[tx][ty + j * 8]);
    }
}

// ==================== fp16 GEMM (128x128 tile, occ 2) ====================
#define GSTR 72
#define G_A   18432                       // 128 rows * 144 B
#define G_STAGE (2 * G_A)                 // 36864
#define G_SMEM  (2 * G_STAGE)             // 73728

__device__ __forceinline__ void gemm_issue(
    uint32_t sb, int tid, const fp16* A1, const fp16* B1,
    int m0, int n0, int kc, int K)
{
#pragma unroll
    for (int i = 0; i < 8; ++i) {
        const int idx = i * 256 + tid;       // 0..2047
        const int arr = idx >> 10;           // 0 = A, 1 = B
        const int rem = idx & 1023;          // 128 rows x 8 segs
        const int row = rem >> 3, seg = rem & 7;
        const fp16* src = arr ? B1 : A1;
        const int grow = (arr ? n0 : m0) + row;
        cp_async16(sb + arr * G_A + (uint32_t)(row * GSTR + seg * 8) * 2,
                   src + (size_t)grow * K + kc + seg * 8);
    }
    cp_commit();
}

template <int MODE>
__global__ __launch_bounds__(256, 2)
void gemm_mma(const fp16* __restrict__ A1, const fp16* __restrict__ B1,
              const float* __restrict__ bias, float* __restrict__ out,
              int N, int K)
{
    extern __shared__ char smc[];
    const uint32_t base = smem_u32(smc);

    const int tid = threadIdx.x, lane = tid & 31, wid = tid >> 5;
    const int wm = wid & 3, wn = wid >> 2;        // 4m x 2n
    const int m0 = blockIdx.y * 128, n0 = blockIdx.x * 128;

    float acc[2][8][4];
#pragma unroll
    for (int t = 0; t < 2; ++t)
#pragma unroll
        for (int n = 0; n < 8; ++n)
#pragma unroll
            for (int j = 0; j < 4; ++j) acc[t][n][j] = 0.f;

    const int a_r  = lane & 15;
    const int a_c8 = (lane >> 4) * 8;
    const int b_r  = (lane & 7) + ((lane >> 4) << 3);
    const int b_c8 = ((lane >> 3) & 1) * 8;

    const int NC = K / 64;                  // 12
    gemm_issue(base, tid, A1, B1, m0, n0, 0, K);

    for (int c = 0; c < NC; ++c) {
        const int buf = c & 1;
        if (c + 1 < NC) {
            gemm_issue(base + (buf ^ 1) * G_STAGE, tid, A1, B1,
                       m0, n0, (c + 1) * 64, K);
            cp_wait<1>();
        } else {
            cp_wait<0>();
        }
        __syncthreads();

        const uint32_t sb = base + buf * G_STAGE;
#pragma unroll
        for (int kf = 0; kf < 4; ++kf) {
            uint32_t af[2][4];
#pragma unroll
            for (int t = 0; t < 2; ++t) {
                const uint32_t off =
                    (uint32_t)((wm * 32 + t * 16 + a_r) * GSTR + kf * 16 + a_c8) * 2;
                ldsm_x4(af[t], sb + off);
            }
#pragma unroll
            for (int nt2 = 0; nt2 < 4; ++nt2) {
                const uint32_t off = G_A +
                    (uint32_t)((wn * 64 + nt2 * 16 + b_r) * GSTR + kf * 16 + b_c8) * 2;
                uint32_t bf[4];
                ldsm_x4(bf, sb + off);
#pragma unroll
                for (int t = 0; t < 2; ++t)
#pragma unroll
                    for (int h = 0; h < 2; ++h)
                        mma16816(acc[t][nt2 * 2 + h], af[t], bf + h * 2);
            }
        }
        __syncthreads();
    }

    // epilogue
#pragma unroll
    for (int t = 0; t < 2; ++t) {
        const int gr0 = m0 + wm * 32 + t * 16 + (lane >> 2);
#pragma unroll
        for (int nt = 0; nt < 8; ++nt) {
            const int gn = n0 + wn * 64 + nt * 8 + 2 * (lane & 3);
            const float b0 = bias[gn], b1 = bias[gn + 1];
            const float v00 = acc[t][nt][0] + b0, v01 = acc[t][nt][1] + b1;
            const float v10 = acc[t][nt][2] + b0, v11 = acc[t][nt][3] + b1;
            if (MODE == 0) {
                *(float2*)&out[(size_t)gr0 * N + gn]       = make_float2(v00, v01);
                *(float2*)&out[(size_t)(gr0 + 8) * N + gn] = make_float2(v10, v11);
            } else {
                const int part = gn / DMODEL;
                const int w = gn % DMODEL;
                const int hh = w >> 6, dd = w & 63;
                const int bb = gr0 >> 11;
                const int ll0 = gr0 & 2047;
                const size_t i0 = (((size_t)bb * NHEADS + hh) * SEQLEN + ll0) * DK + dd;
                const size_t i1 = i0 + 8 * DK;
                fp16* dst = (part == 0) ? g_qs : (part == 1) ? g_ks : g_vs;
                *(uint32_t*)(dst + i0) = pack2h(v00, v01);
                *(uint32_t*)(dst + i1) = pack2h(v10, v11);
            }
        }
    }
}

// ==================== flash attention (fp16, BM=64, occ 4) ==============
// 128 threads / 4 warps; each warp owns 16 rows. 2 KV stages of 64 cols.
// Grid = 768 CTAs on 592 occ-4 slots -> makespan ~1 full-tile-time.
#define KV_STG    18432                   // k 9216 | v 9216
#define ATT_Q     0                       // 64 rows * 144 B = 9216
#define ATT_KV    9216
#define ATT_MASK  (9216 + 2 * KV_STG)     // 46080
#define ATT_SMEM  (ATT_MASK + 512)        // 46592
#define SCALE_L2E 0.1803368867f           // 0.125 * log2(e)

__device__ __forceinline__ void attn_issue_kv(
    uint32_t base, int tid, const fp16* Ks, const fp16* Vs,
    const int* amask_row, int kb, int buf)
{
    const uint32_t sb = base + ATT_KV + buf * KV_STG;
#pragma unroll
    for (int i = 0; i < 8; ++i) {
        const int idx = i * 128 + tid;      // 2 arrays x 512
        const int arr = idx >> 9;
        const int rem = idx & 511;
        const int row = rem >> 3, seg = rem & 7;
        const fp16* src = arr ? Vs : Ks;
        cp_async16(sb + arr * 9216 + (uint32_t)(row * GSTR + seg * 8) * 2,
                   src + (size_t)(kb + row) * DK + seg * 8);
    }
    if (tid < 16)
        cp_async16(base + ATT_MASK + buf * 256 + tid * 16, amask_row + kb + tid * 4);
    cp_commit();
}

__global__ __launch_bounds__(128, 4)
void attn_mma(const int* __restrict__ amask)
{
    extern __shared__ char smc[];
    const uint32_t base = smem_u32(smc);

    const int tid = threadIdx.x, lane = tid & 31, wid = tid >> 5;  // wid 0..3
    const int bh = blockIdx.y, b = bh / NHEADS, h = bh % NHEADS;
    const int qb = blockIdx.x * 64;

    const fp16* Qs = g_qs + (size_t)bh * SEQLEN * DK;
    const fp16* Ks = g_ks + (size_t)bh * SEQLEN * DK;
    const fp16* Vs = g_vs + (size_t)bh * SEQLEN * DK;
    const int* amask_row = amask + (size_t)b * SEQLEN;

    // prologue G0: Q (64 rows) + KV chunk 0 + mask 0 (one commit)
#pragma unroll
    for (int i = 0; i < 4; ++i) {
        const int idx = i * 128 + tid;          // 0..511
        const int row = idx >> 3, seg = idx & 7;
        cp_async16(base + ATT_Q + (uint32_t)(row * GSTR + seg * 8) * 2,
                   Qs + (size_t)(qb + row) * DK + seg * 8);
    }
    attn_issue_kv(base, tid, Ks, Vs, amask_row, 0, 0);

    float m0s = -1e30f, m1s = -1e30f, l0s = 0.f, l1s = 0.f;
    float oacc[8][4];
#pragma unroll
    for (int n = 0; n < 8; ++n)
#pragma unroll
        for (int j = 0; j < 4; ++j) oacc[n][j] = 0.f;

    const int a_r  = lane & 15;
    const int a_c8 = (lane >> 4) * 8;
    const int kb_r = (lane & 7) + ((lane >> 4) << 3);
    const int kb_c8 = ((lane >> 3) & 1) * 8;
    const int vb_r = (lane & 7) + ((lane >> 3) & 1) * 8;
    const int vb_c8 = (lane >> 4) * 8;
    const int mrow = wid * 16;
    const int cbase = 2 * (lane & 3);

    const int NIT = SEQLEN / 64;   // 32
    for (int it = 0; it < NIT; ++it) {
        const int buf = it & 1;
        if (it + 1 < NIT) {
            attn_issue_kv(base, tid, Ks, Vs, amask_row, (it + 1) * 64, buf ^ 1);
            cp_wait<1>();
        } else {
            cp_wait<0>();
        }
        __syncthreads();

        const uint32_t kvb = base + ATT_KV + buf * KV_STG;
        const int* smask = (const int*)(smc + ATT_MASK + buf * 256);

        // ---- S = Q @ K^T ----
        float sacc[8][4];
#pragma unroll
        for (int n = 0; n < 8; ++n)
#pragma unroll
            for (int j = 0; j < 4; ++j) sacc[n][j] = 0.f;

#pragma unroll
        for (int kf = 0; kf < 4; ++kf) {
            uint32_t qf[4];
            const uint32_t qoff = (uint32_t)((mrow + a_r) * GSTR + kf * 16 + a_c8) * 2;
            ldsm_x4(qf, base + ATT_Q + qoff);
#pragma unroll
            for (int np = 0; np < 2; ++np) {             // nt2 pair {2np, 2np+1}
                uint32_t kf4[2][4];
#pragma unroll
                for (int j = 0; j < 2; ++j) {
                    const int nt2 = np * 2 + j;
                    const uint32_t koff =
                        (uint32_t)((nt2 * 16 + kb_r) * GSTR + kf * 16 + kb_c8) * 2;
                    ldsm_x4(kf4[j], kvb + koff);
                }
#pragma unroll
                for (int j = 0; j < 2; ++j)
#pragma unroll
                    for (int hh = 0; hh < 2; ++hh)
                        mma16816(sacc[np * 4 + j * 2 + hh], qf, kf4[j] + hh * 2);
            }
        }

        // ---- scale (log2 domain) + mask ----
#pragma unroll
        for (int nt = 0; nt < 8; ++nt) {
            const float ma = smask[nt * 8 + cbase]     ? 0.f : -1e30f;
            const float mb = smask[nt * 8 + cbase + 1] ? 0.f : -1e30f;
            sacc[nt][0] = sacc[nt][0] * SCALE_L2E + ma;
            sacc[nt][1] = sacc[nt][1] * SCALE_L2E + mb;
            sacc[nt][2] = sacc[nt][2] * SCALE_L2E + ma;
            sacc[nt][3] = sacc[nt][3] * SCALE_L2E + mb;
        }

        // ---- online softmax (rows r=lane>>2 and r+8), exp2 in-place ----
        float mx0 = -1e30f, mx1 = -1e30f;
#pragma unroll
        for (int nt = 0; nt < 8; ++nt) {
            mx0 = fmaxf(mx0, fmaxf(sacc[nt][0], sacc[nt][1]));
            mx1 = fmaxf(mx1, fmaxf(sacc[nt][2], sacc[nt][3]));
        }
        mx0 = fmaxf(mx0, __shfl_xor_sync(0xffffffffu, mx0, 1));
        mx0 = fmaxf(mx0, __shfl_xor_sync(0xffffffffu, mx0, 2));
        mx1 = fmaxf(mx1, __shfl_xor_sync(0xffffffffu, mx1, 1));
        mx1 = fmaxf(mx1, __shfl_xor_sync(0xffffffffu, mx1, 2));
        const float mn0 = fmaxf(m0s, mx0), mn1 = fmaxf(m1s, mx1);
        const float al0 = exp2f(m0s - mn0), al1 = exp2f(m1s - mn1);
        m0s = mn0; m1s = mn1;

        float rs0 = 0.f, rs1 = 0.f;
#pragma unroll
        for (int nt = 0; nt < 8; ++nt) {
            sacc[nt][0] = exp2f(sacc[nt][0] - mn0);
            sacc[nt][1] = exp2f(sacc[nt][1] - mn0);
            sacc[nt][2] = exp2f(sacc[nt][2] - mn1);
            sacc[nt][3] = exp2f(sacc[nt][3] - mn1);
            rs0 += sacc[nt][0] + sacc[nt][1];
            rs1 += sacc[nt][2] + sacc[nt][3];
        }
        rs0 += __shfl_xor_sync(0xffffffffu, rs0, 1);
        rs0 += __shfl_xor_sync(0xffffffffu, rs0, 2);
        rs1 += __shfl_xor_sync(0xffffffffu, rs1, 1);
        rs1 += __shfl_xor_sync(0xffffffffu, rs1, 2);
        l0s = l0s * al0 + rs0;
        l1s = l1s * al1 + rs1;
#pragma unroll
        for (int nt = 0; nt < 8; ++nt) {
            oacc[nt][0] *= al0; oacc[nt][1] *= al0;
            oacc[nt][2] *= al1; oacc[nt][3] *= al1;
        }

        // ---- O += P @ V (P single fp16) ----
#pragma unroll
        for (int kf2 = 0; kf2 < 4; ++kf2) {
            uint32_t pf[4];
            pf[0] = pack2h(sacc[2 * kf2][0],     sacc[2 * kf2][1]);
            pf[1] = pack2h(sacc[2 * kf2][2],     sacc[2 * kf2][3]);
            pf[2] = pack2h(sacc[2 * kf2 + 1][0], sacc[2 * kf2 + 1][1]);
            pf[3] = pack2h(sacc[2 * kf2 + 1][2], sacc[2 * kf2 + 1][3]);
#pragma unroll
            for (int dp = 0; dp < 2; ++dp) {             // dt2 pair {2dp, 2dp+1}
                uint32_t vf4[2][4];
#pragma unroll
                for (int j = 0; j < 2; ++j) {
                    const int dt2 = dp * 2 + j;
                    const uint32_t voff =
                        (uint32_t)((kf2 * 16 + vb_r) * GSTR + dt2 * 16 + vb_c8) * 2;
                    ldsm_x4t(vf4[j], kvb + 9216 + voff);
                }
#pragma unroll
                for (int j = 0; j < 2; ++j)
#pragma unroll
                    for (int hh = 0; hh < 2; ++hh)
                        mma16816(oacc[dp * 4 + j * 2 + hh], pf, vf4[j] + hh * 2);
            }
        }
        __syncthreads();   // done reading buf before refill
    }

    // epilogue: O /= l, store fp16 in (B,L,D)
    const float inv0 = 1.f / l0s, inv1 = 1.f / l1s;
    const int row0 = qb + mrow + (lane >> 2);
#pragma unroll
    for (int dt = 0; dt < 8; ++dt) {
        const int col = h * DK + dt * 8 + 2 * (lane & 3);
        const size_t i0 = ((size_t)b * SEQLEN + row0) * DMODEL + col;
        const size_t i1 = i0 + (size_t)8 * DMODEL;
        *(uint32_t*)(g_os + i0) = pack2h(oacc[dt][0] * inv0, oacc[dt][1] * inv0);
        *(uint32_t*)(g_os + i1) = pack2h(oacc[dt][2] * inv1, oacc[dt][3] * inv1);
    }
}

// ==================== launch ====================
extern "C" void kernel_launch(void* const* d_in, const int* in_sizes, int n_in,
                              void* d_out, int out_size)
{
    const float* x     = (const float*)d_in[0];
    const int*   amask = (const int*)  d_in[1];
    const float* w_qkv = (const float*)d_in[2];
    const float* b_qkv = (const float*)d_in[3];
    const float* w_out = (const float*)d_in[4];
    const float* b_out = (const float*)d_in[5];
    float*       out   = (float*)d_out;

    fp16 *x1, *wq, *wo, *os;
    cudaGetSymbolAddress((void**)&x1, g_x1);
    cudaGetSymbolAddress((void**)&wq, g_wq);
    cudaGetSymbolAddress((void**)&wo, g_wo);
    cudaGetSymbolAddress((void**)&os, g_os);

    // 0) prep: x -> fp16, W -> transposed fp16
    const int n4 = MTOT * DMODEL / 4;
    conv_x_kernel<<<(n4 + 255) / 256, 256>>>(x, x1, n4);
    ttrans_kernel<<<dim3(3 * DMODEL / 32, DMODEL / 32), 256>>>(w_qkv, wq, DMODEL, 3 * DMODEL);
    ttrans_kernel<<<dim3(DMODEL / 32, DMODEL / 32), 256>>>(w_out, wo, DMODEL, DMODEL);

    // 1) QKV projection (fp16, 128x128 tiles, occ 2)
    cudaFuncSetAttribute(gemm_mma<1>, cudaFuncAttributeMaxDynamicSharedMemorySize, G_SMEM);
    gemm_mma<1><<<dim3(3 * DMODEL / 128, MTOT / 128), 256, G_SMEM>>>(
        x1, wq, b_qkv, nullptr, 3 * DMODEL, DMODEL);

    // 2) flash attention (fp16, BM=64, occ 4)
    cudaFuncSetAttribute(attn_mma, cudaFuncAttributeMaxDynamicSharedMemorySize, ATT_SMEM);
    attn_mma<<<dim3(SEQLEN / 64, BATCH * NHEADS), 128, ATT_SMEM>>>(amask);

    // 3) output projection (fp16, 128x128 tiles)
    cudaFuncSetAttribute(gemm_mma<0>, cudaFuncAttributeMaxDynamicSharedMemorySize, G_SMEM);
    gemm_mma<0><<<dim3(DMODEL / 128, MTOT / 128), 256, G_SMEM>>>(
        os, wo, b_out, out, DMODEL, DMODEL);
}

// round 17
// speedup vs baseline: 3.8110x; 1.0183x over previous
#include <cuda_runtime.h>
#include <cuda_fp16.h>
#include <cstdint>

#define BATCH   2
#define NHEADS  12
#define SEQLEN  2048
#define DMODEL  768
#define DK      64
#define MTOT    (BATCH * SEQLEN)          // 4096

typedef __half fp16;

// ---------------- scratch (no allocations allowed) ----------------
__device__ __align__(256) fp16 g_x1[(size_t)MTOT * DMODEL];          // x fp16
__device__ __align__(256) fp16 g_wq[(size_t)3 * DMODEL * DMODEL];    // W_qkv^T [N][K]
__device__ __align__(256) fp16 g_wo[(size_t)DMODEL * DMODEL];        // W_out^T [N][K]
__device__ __align__(256) fp16 g_qs[(size_t)BATCH * NHEADS * SEQLEN * DK];
__device__ __align__(256) fp16 g_ks[(size_t)BATCH * NHEADS * SEQLEN * DK];
__device__ __align__(256) fp16 g_vs[(size_t)BATCH * NHEADS * SEQLEN * DK];
__device__ __align__(256) fp16 g_os[(size_t)MTOT * DMODEL];          // O fp16

// ==================== helpers ====================
__device__ __forceinline__ uint32_t smem_u32(const void* p) {
    uint32_t a;
    asm("{ .reg .u64 t; cvta.to.shared.u64 t, %1; cvt.u32.u64 %0, t; }" : "=r"(a) : "l"(p));
    return a;
}
__device__ __forceinline__ void mma16816(float* d, const uint32_t* a, const uint32_t* b) {
    asm volatile(
        "mma.sync.aligned.m16n8k16.row.col.f32.f16.f16.f32 "
        "{%0,%1,%2,%3}, {%4,%5,%6,%7}, {%8,%9}, {%0,%1,%2,%3};"
        : "+f"(d[0]), "+f"(d[1]), "+f"(d[2]), "+f"(d[3])
        : "r"(a[0]), "r"(a[1]), "r"(a[2]), "r"(a[3]), "r"(b[0]), "r"(b[1]));
}
__device__ __forceinline__ void ldsm_x4(uint32_t* r, uint32_t addr) {
    asm volatile("ldmatrix.sync.aligned.m8n8.x4.shared.b16 {%0,%1,%2,%3}, [%4];"
                 : "=r"(r[0]), "=r"(r[1]), "=r"(r[2]), "=r"(r[3]) : "r"(addr));
}
__device__ __forceinline__ void ldsm_x4t(uint32_t* r, uint32_t addr) {
    asm volatile("ldmatrix.sync.aligned.m8n8.x4.trans.shared.b16 {%0,%1,%2,%3}, [%4];"
                 : "=r"(r[0]), "=r"(r[1]), "=r"(r[2]), "=r"(r[3]) : "r"(addr));
}
__device__ __forceinline__ void cp_async16(uint32_t dst, const void* src) {
    asm volatile("cp.async.cg.shared.global [%0], [%1], 16;" :: "r"(dst), "l"(src));
}
__device__ __forceinline__ void cp_commit() {
    asm volatile("cp.async.commit_group;" ::: "memory");
}
template <int N>
__device__ __forceinline__ void cp_wait() {
    asm volatile("cp.async.wait_group %0;" :: "n"(N) : "memory");
}
__device__ __forceinline__ uint32_t pack2h(float x, float y) {
    __half2 hh = __floats2half2_rn(x, y);
    return *reinterpret_cast<uint32_t*>(&hh);
}

// ==================== fused prep kernel ====================
// blocks [0, 3072):       x fp32 -> fp16
// blocks [3072, 4800):    W_qkv transpose+convert  (72 x 24 tiles)
// blocks [4800, 5376):    W_out transpose+convert  (24 x 24 tiles)
#define PREP_CONV_BLKS 3072
#define PREP_WQ_BLKS   1728
#define PREP_GRID      5376

__device__ __forceinline__ void prep_tsplit(
    const float* __restrict__ W, fp16* __restrict__ T,
    int K, int N, int bn, int bk, int tid)
{
    __shared__ float t[32][33];
    const int tx = tid & 31, ty = tid >> 5;
#pragma unroll
    for (int j = 0; j < 4; ++j)
        t[ty + j * 8][tx] = W[(size_t)(bk + ty + j * 8) * N + bn + tx];
    __syncthreads();
#pragma unroll
    for (int j = 0; j < 4; ++j) {
        const int n = bn + ty + j * 8;
        const int k = bk + tx;
        T[(size_t)n * K + k] = __float2half_rn(t[tx][ty + j * 8]);
    }
}

__global__ void prep_kernel(const float* __restrict__ x, fp16* __restrict__ x1,
                            const float* __restrict__ wq_in, fp16* __restrict__ wq,
                            const float* __restrict__ wo_in, fp16* __restrict__ wo)
{
    const int bid = blockIdx.x, tid = threadIdx.x;
    if (bid < PREP_CONV_BLKS) {
        const int i = bid * 256 + tid;            // < MTOT*DMODEL/4
        float4 v = ((const float4*)x)[i];
        ((uint32_t*)x1)[i * 2 + 0] = pack2h(v.x, v.y);
        ((uint32_t*)x1)[i * 2 + 1] = pack2h(v.z, v.w);
    } else if (bid < PREP_CONV_BLKS + PREP_WQ_BLKS) {
        const int t = bid - PREP_CONV_BLKS;       // 72 n-tiles x 24 k-tiles
        prep_tsplit(wq_in, wq, DMODEL, 3 * DMODEL, (t % 72) * 32, (t / 72) * 32, tid);
    } else {
        const int t = bid - PREP_CONV_BLKS - PREP_WQ_BLKS;  // 24 x 24
        prep_tsplit(wo_in, wo, DMODEL, DMODEL, (t % 24) * 32, (t / 24) * 32, tid);
    }
}

// ==================== fp16 GEMM (128x128 tile, 3-stage, occ 2) ===========
#define GSTR 72
#define G_A   18432                       // 128 rows * 144 B
#define G_STAGE (2 * G_A)                 // 36864
#define G_SMEM  (3 * G_STAGE)             // 110592

__device__ __forceinline__ void gemm_issue(
    uint32_t sb, int tid, const fp16* A1, const fp16* B1,
    int m0, int n0, int kc, int K)
{
#pragma unroll
    for (int i = 0; i < 8; ++i) {
        const int idx = i * 256 + tid;       // 0..2047
        const int arr = idx >> 10;           // 0 = A, 1 = B
        const int rem = idx & 1023;          // 128 rows x 8 segs
        const int row = rem >> 3, seg = rem & 7;
        const fp16* src = arr ? B1 : A1;
        const int grow = (arr ? n0 : m0) + row;
        cp_async16(sb + arr * G_A + (uint32_t)(row * GSTR + seg * 8) * 2,
                   src + (size_t)grow * K + kc + seg * 8);
    }
    cp_commit();
}

template <int MODE>
__global__ __launch_bounds__(256, 2)
void gemm_mma(const fp16* __restrict__ A1, const fp16* __restrict__ B1,
              const float* __restrict__ bias, float* __restrict__ out,
              int N, int K)
{
    extern __shared__ char smc[];
    const uint32_t base = smem_u32(smc);

    const int tid = threadIdx.x, lane = tid & 31, wid = tid >> 5;
    const int wm = wid & 3, wn = wid >> 2;        // 4m x 2n
    const int m0 = blockIdx.y * 128, n0 = blockIdx.x * 128;

    float acc[2][8][4];
#pragma unroll
    for (int t = 0; t < 2; ++t)
#pragma unroll
        for (int n = 0; n < 8; ++n)
#pragma unroll
            for (int j = 0; j < 4; ++j) acc[t][n][j] = 0.f;

    const int a_r  = lane & 15;
    const int a_c8 = (lane >> 4) * 8;
    const int b_r  = (lane & 7) + ((lane >> 4) << 3);
    const int b_c8 = ((lane >> 3) & 1) * 8;

    const int NC = K / 64;                  // 12
    gemm_issue(base, tid, A1, B1, m0, n0, 0, K);
    gemm_issue(base + G_STAGE, tid, A1, B1, m0, n0, 64, K);

    int sidx = 0;
    for (int c = 0; c < NC; ++c) {
        if (c + 1 < NC) cp_wait<1>(); else cp_wait<0>();
        __syncthreads();        // chunk c visible; stage (c-1)%3 readers done
        if (c + 2 < NC) {
            const int s2 = (sidx + 2) % 3;
            gemm_issue(base + s2 * G_STAGE, tid, A1, B1, m0, n0, (c + 2) * 64, K);
        }

        const uint32_t sb = base + sidx * G_STAGE;
#pragma unroll
        for (int kf = 0; kf < 4; ++kf) {
            uint32_t af[2][4];
#pragma unroll
            for (int t = 0; t < 2; ++t) {
                const uint32_t off =
                    (uint32_t)((wm * 32 + t * 16 + a_r) * GSTR + kf * 16 + a_c8) * 2;
                ldsm_x4(af[t], sb + off);
            }
#pragma unroll
            for (int nt2 = 0; nt2 < 4; ++nt2) {
                const uint32_t off = G_A +
                    (uint32_t)((wn * 64 + nt2 * 16 + b_r) * GSTR + kf * 16 + b_c8) * 2;
                uint32_t bf[4];
                ldsm_x4(bf, sb + off);
#pragma unroll
                for (int t = 0; t < 2; ++t)
#pragma unroll
                    for (int h = 0; h < 2; ++h)
                        mma16816(acc[t][nt2 * 2 + h], af[t], bf + h * 2);
            }
        }
        sidx = (sidx == 2) ? 0 : sidx + 1;
    }

    // epilogue
#pragma unroll
    for (int t = 0; t < 2; ++t) {
        const int gr0 = m0 + wm * 32 + t * 16 + (lane >> 2);
#pragma unroll
        for (int nt = 0; nt < 8; ++nt) {
            const int gn = n0 + wn * 64 + nt * 8 + 2 * (lane & 3);
            const float b0 = bias[gn], b1 = bias[gn + 1];
            const float v00 = acc[t][nt][0] + b0, v01 = acc[t][nt][1] + b1;
            const float v10 = acc[t][nt][2] + b0, v11 = acc[t][nt][3] + b1;
            if (MODE == 0) {
                *(float2*)&out[(size_t)gr0 * N + gn]       = make_float2(v00, v01);
                *(float2*)&out[(size_t)(gr0 + 8) * N + gn] = make_float2(v10, v11);
            } else {
                const int part = gn / DMODEL;
                const int w = gn % DMODEL;
                const int hh = w >> 6, dd = w & 63;
                const int bb = gr0 >> 11;
                const int ll0 = gr0 & 2047;
                const size_t i0 = (((size_t)bb * NHEADS + hh) * SEQLEN + ll0) * DK + dd;
                const size_t i1 = i0 + 8 * DK;
                fp16* dst = (part == 0) ? g_qs : (part == 1) ? g_ks : g_vs;
                *(uint32_t*)(dst + i0) = pack2h(v00, v01);
                *(uint32_t*)(dst + i1) = pack2h(v10, v11);
            }
        }
    }
}

// ==================== flash attention (fp16, BM=64, occ 4, Q in regs) ===
#define KV_STG    18432                   // k 9216 | v 9216
#define ATT_Q     0                       // 64 rows * 144 B = 9216
#define ATT_KV    9216
#define ATT_MASK  (9216 + 2 * KV_STG)     // 46080
#define ATT_SMEM  (ATT_MASK + 512)        // 46592
#define SCALE_L2E 0.1803368867f           // 0.125 * log2(e)

__device__ __forceinline__ void attn_issue_kv(
    uint32_t base, int tid, const fp16* Ks, const fp16* Vs,
    const int* amask_row, int kb, int buf)
{
    const uint32_t sb = base + ATT_KV + buf * KV_STG;
#pragma unroll
    for (int i = 0; i < 8; ++i) {
        const int idx = i * 128 + tid;      // 2 arrays x 512
        const int arr = idx >> 9;
        const int rem = idx & 511;
        const int row = rem >> 3, seg = rem & 7;
        const fp16* src = arr ? Vs : Ks;
        cp_async16(sb + arr * 9216 + (uint32_t)(row * GSTR + seg * 8) * 2,
                   src + (size_t)(kb + row) * DK + seg * 8);
    }
    if (tid < 16)
        cp_async16(base + ATT_MASK + buf * 256 + tid * 16, amask_row + kb + tid * 4);
    cp_commit();
}

__global__ __launch_bounds__(128, 4)
void attn_mma(const int* __restrict__ amask)
{
    extern __shared__ char smc[];
    const uint32_t base = smem_u32(smc);

    const int tid = threadIdx.x, lane = tid & 31, wid = tid >> 5;  // wid 0..3
    const int bh = blockIdx.y, b = bh / NHEADS, h = bh % NHEADS;
    const int qb = blockIdx.x * 64;

    const fp16* Qs = g_qs + (size_t)bh * SEQLEN * DK;
    const fp16* Ks = g_ks + (size_t)bh * SEQLEN * DK;
    const fp16* Vs = g_vs + (size_t)bh * SEQLEN * DK;
    const int* amask_row = amask + (size_t)b * SEQLEN;

    // prologue G0: Q (64 rows) + KV chunk 0 + mask 0; G1: KV chunk 1
#pragma unroll
    for (int i = 0; i < 4; ++i) {
        const int idx = i * 128 + tid;          // 0..511
        const int row = idx >> 3, seg = idx & 7;
        cp_async16(base + ATT_Q + (uint32_t)(row * GSTR + seg * 8) * 2,
                   Qs + (size_t)(qb + row) * DK + seg * 8);
    }
    attn_issue_kv(base, tid, Ks, Vs, amask_row, 0, 0);   // commits G0
    attn_issue_kv(base, tid, Ks, Vs, amask_row, 64, 1);  // G1

    const int a_r  = lane & 15;
    const int a_c8 = (lane >> 4) * 8;
    const int kb_r = (lane & 7) + ((lane >> 4) << 3);
    const int kb_c8 = ((lane >> 3) & 1) * 8;
    const int vb_r = (lane & 7) + ((lane >> 3) & 1) * 8;
    const int vb_c8 = (lane >> 4) * 8;
    const int mrow = wid * 16;
    const int cbase = 2 * (lane & 3);

    // wait for G0 (Q + KV0), then hoist Q fragments into registers
    cp_wait<1>();
    __syncthreads();
    uint32_t qreg[4][4];
#pragma unroll
    for (int kf = 0; kf < 4; ++kf) {
        const uint32_t qoff = (uint32_t)((mrow + a_r) * GSTR + kf * 16 + a_c8) * 2;
        ldsm_x4(qreg[kf], base + ATT_Q + qoff);
    }

    float m0s = -1e30f, m1s = -1e30f, l0s = 0.f, l1s = 0.f;
    float oacc[8][4];
#pragma unroll
    for (int n = 0; n < 8; ++n)
#pragma unroll
        for (int j = 0; j < 4; ++j) oacc[n][j] = 0.f;

    const int NIT = SEQLEN / 64;   // 32
    for (int it = 0; it < NIT; ++it) {
        const int buf = it & 1;
        if (it + 1 < NIT) cp_wait<1>(); else cp_wait<0>();
        __syncthreads();    // chunk it visible to all

        const uint32_t kvb = base + ATT_KV + buf * KV_STG;
        const int* smask = (const int*)(smc + ATT_MASK + buf * 256);

        // ---- S = Q @ K^T ----
        float sacc[8][4];
#pragma unroll
        for (int n = 0; n < 8; ++n)
#pragma unroll
            for (int j = 0; j < 4; ++j) sacc[n][j] = 0.f;

#pragma unroll
        for (int kf = 0; kf < 4; ++kf) {
#pragma unroll
            for (int np = 0; np < 2; ++np) {             // nt2 pair {2np, 2np+1}
                uint32_t kf4[2][4];
#pragma unroll
                for (int j = 0; j < 2; ++j) {
                    const int nt2 = np * 2 + j;
                    const uint32_t koff =
                        (uint32_t)((nt2 * 16 + kb_r) * GSTR + kf * 16 + kb_c8) * 2;
                    ldsm_x4(kf4[j], kvb + koff);
                }
#pragma unroll
                for (int j = 0; j < 2; ++j)
#pragma unroll
                    for (int hh = 0; hh < 2; ++hh)
                        mma16816(sacc[np * 4 + j * 2 + hh], qreg[kf], kf4[j] + hh * 2);
            }
        }

        // ---- scale (log2 domain) + mask ----
#pragma unroll
        for (int nt = 0; nt < 8; ++nt) {
            const float ma = smask[nt * 8 + cbase]     ? 0.f : -1e30f;
            const float mb = smask[nt * 8 + cbase + 1] ? 0.f : -1e30f;
            sacc[nt][0] = sacc[nt][0] * SCALE_L2E + ma;
            sacc[nt][1] = sacc[nt][1] * SCALE_L2E + mb;
            sacc[nt][2] = sacc[nt][2] * SCALE_L2E + ma;
            sacc[nt][3] = sacc[nt][3] * SCALE_L2E + mb;
        }

        // ---- online softmax (rows r=lane>>2 and r+8), exp2 in-place ----
        float mx0 = -1e30f, mx1 = -1e30f;
#pragma unroll
        for (int nt = 0; nt < 8; ++nt) {
            mx0 = fmaxf(mx0, fmaxf(sacc[nt][0], sacc[nt][1]));
            mx1 = fmaxf(mx1, fmaxf(sacc[nt][2], sacc[nt][3]));
        }
        mx0 = fmaxf(mx0, __shfl_xor_sync(0xffffffffu, mx0, 1));
        mx0 = fmaxf(mx0, __shfl_xor_sync(0xffffffffu, mx0, 2));
        mx1 = fmaxf(mx1, __shfl_xor_sync(0xffffffffu, mx1, 1));
        mx1 = fmaxf(mx1, __shfl_xor_sync(0xffffffffu, mx1, 2));
        const float mn0 = fmaxf(m0s, mx0), mn1 = fmaxf(m1s, mx1);
        const float al0 = exp2f(m0s - mn0), al1 = exp2f(m1s - mn1);
        m0s = mn0; m1s = mn1;

        float rs0 = 0.f, rs1 = 0.f;
#pragma unroll
        for (int nt = 0; nt < 8; ++nt) {
            sacc[nt][0] = exp2f(sacc[nt][0] - mn0);
            sacc[nt][1] = exp2f(sacc[nt][1] - mn0);
            sacc[nt][2] = exp2f(sacc[nt][2] - mn1);
            sacc[nt][3] = exp2f(sacc[nt][3] - mn1);
            rs0 += sacc[nt][0] + sacc[nt][1];
            rs1 += sacc[nt][2] + sacc[nt][3];
        }
        rs0 += __shfl_xor_sync(0xffffffffu, rs0, 1);
        rs0 += __shfl_xor_sync(0xffffffffu, rs0, 2);
        rs1 += __shfl_xor_sync(0xffffffffu, rs1, 1);
        rs1 += __shfl_xor_sync(0xffffffffu, rs1, 2);
        l0s = l0s * al0 + rs0;
        l1s = l1s * al1 + rs1;
#pragma unroll
        for (int nt = 0; nt < 8; ++nt) {
            oacc[nt][0] *= al0; oacc[nt][1] *= al0;
            oacc[nt][2] *= al1; oacc[nt][3] *= al1;
        }

        // ---- O += P @ V (P single fp16) ----
#pragma unroll
        for (int kf2 = 0; kf2 < 4; ++kf2) {
            uint32_t pf[4];
            pf[0] = pack2h(sacc[2 * kf2][0],     sacc[2 * kf2][1]);
            pf[1] = pack2h(sacc[2 * kf2][2],     sacc[2 * kf2][3]);
            pf[2] = pack2h(sacc[2 * kf2 + 1][0], sacc[2 * kf2 + 1][1]);
            pf[3] = pack2h(sacc[2 * kf2 + 1][2], sacc[2 * kf2 + 1][3]);
#pragma unroll
            for (int dp = 0; dp < 2; ++dp) {             // dt2 pair {2dp, 2dp+1}
                uint32_t vf4[2][4];
#pragma unroll
                for (int j = 0; j < 2; ++j) {
                    const int dt2 = dp * 2 + j;
                    const uint32_t voff =
                        (uint32_t)((kf2 * 16 + vb_r) * GSTR + dt2 * 16 + vb_c8) * 2;
                    ldsm_x4t(vf4[j], kvb + 9216 + voff);
                }
#pragma unroll
                for (int j = 0; j < 2; ++j)
#pragma unroll
                    for (int hh = 0; hh < 2; ++hh)
                        mma16816(oacc[dp * 4 + j * 2 + hh], pf, vf4[j] + hh * 2);
            }
        }
        __syncthreads();    // all warps done reading buf
        if (it + 2 < NIT)
            attn_issue_kv(base, tid, Ks, Vs, amask_row, (it + 2) * 64, buf);
    }

    // epilogue: O /= l, store fp16 in (B,L,D)
    const float inv0 = 1.f / l0s, inv1 = 1.f / l1s;
    const int row0 = qb + mrow + (lane >> 2);
#pragma unroll
    for (int dt = 0; dt < 8; ++dt) {
        const int col = h * DK + dt * 8 + 2 * (lane & 3);
        const size_t i0 = ((size_t)b * SEQLEN + row0) * DMODEL + col;
        const size_t i1 = i0 + (size_t)8 * DMODEL;
        *(uint32_t*)(g_os + i0) = pack2h(oacc[dt][0] * inv0, oacc[dt][1] * inv0);
        *(uint32_t*)(g_os + i1) = pack2h(oacc[dt][2] * inv1, oacc[dt][3] * inv1);
    }
}

// ==================== launch ====================
extern "C" void kernel_launch(void* const* d_in, const int* in_sizes, int n_in,
                              void* d_out, int out_size)
{
    const float* x     = (const float*)d_in[0];
    const int*   amask = (const int*)  d_in[1];
    const float* w_qkv = (const float*)d_in[2];
    const float* b_qkv = (const float*)d_in[3];
    const float* w_out = (const float*)d_in[4];
    const float* b_out = (const float*)d_in[5];
    float*       out   = (float*)d_out;

    fp16 *x1, *wq, *wo, *os;
    cudaGetSymbolAddress((void**)&x1, g_x1);
    cudaGetSymbolAddress((void**)&wq, g_wq);
    cudaGetSymbolAddress((void**)&wo, g_wo);
    cudaGetSymbolAddress((void**)&os, g_os);

    // 0) fused prep: x -> fp16; W_qkv, W_out -> transposed fp16
    prep_kernel<<<PREP_GRID, 256>>>(x, x1, w_qkv, wq, w_out, wo);

    // 1) QKV projection (fp16, 128x128 tiles, 3-stage, occ 2)
    cudaFuncSetAttribute(gemm_mma<1>, cudaFuncAttributeMaxDynamicSharedMemorySize, G_SMEM);
    gemm_mma<1><<<dim3(3 * DMODEL / 128, MTOT / 128), 256, G_SMEM>>>(
        x1, wq, b_qkv, nullptr, 3 * DMODEL, DMODEL);

    // 2) flash attention (fp16, BM=64, occ 4, Q in regs)
    cudaFuncSetAttribute(attn_mma, cudaFuncAttributeMaxDynamicSharedMemorySize, ATT_SMEM);
    attn_mma<<<dim3(SEQLEN / 64, BATCH * NHEADS), 128, ATT_SMEM>>>(amask);

    // 3) output projection (fp16, 128x128 tiles, 3-stage)
    cudaFuncSetAttribute(gemm_mma<0>, cudaFuncAttributeMaxDynamicSharedMemorySize, G_SMEM);
    gemm_mma<0><<<dim3(DMODEL / 128, MTOT / 128), 256, G_SMEM>>>(
        os, wo, b_out, out, DMODEL, DMODEL);
}